// round 9
// baseline (speedup 1.0000x reference)
#include <cuda_runtime.h>
#include <cuda_bf16.h>
#include <cstdint>

// LuGreCell: B=4096, T=2048, S=1, H=64.
// K1 lugre_pre : per (b,t) v,k,c2,Fs -> time-major [T][B] float4 (HBM-bound).
// K2 lugre_tab : tabulate Lg(v,sz)=softplus(MLP(v,sz))*log2e on 2049x513 grid
//                (the MLP is a fixed smooth 2D function shared by all steps).
// K3 lugre_pack: pack bilinear quads (l00,l01,l10,l11) into float4 cells.
// K4 lugre_scan: 128 warps (1/SM), 32 batches/warp (one per lane).
//                Depth-8 pipeline: slot (c_a,c_b) for step i+8 built at
//                pred=S_i from ONE float4 table gather; on-chain per step:
//                szn = fma(c_b,S,c_a); clamp.  (~12 cyc chain)

#define BB 4096
#define TT 2048
#define HH 64

// table geometry
#define NVC 2048            /* v cells   */
#define NSC 512             /* sz cells  */
#define VMIN   (-8.0f)
#define DV     (16.0f / 2048.0f)
#define INV_DV 128.0f
#define OFF_V  1024.0f      /* -VMIN*INV_DV */
#define SZMIN  (-2.6f)
#define DSZ    (5.2f / 512.0f)
#define INV_DSZ 98.46153846153847f
#define OFF_S  256.0f       /* -SZMIN*INV_DSZ */

__device__ float4 g_pre[(size_t)BB * TT];            // 134 MB scratch
__device__ float  g_Ls[(NVC + 1) * (NSC + 1)];       // 4.2 MB scalar table
__device__ float4 g_tab4[(size_t)NVC * NSC];         // 16.8 MB packed quads

__device__ __forceinline__ float ex2f_(float x){ float y; asm("ex2.approx.f32 %0, %1;":"=f"(y):"f"(x)); return y; }
__device__ __forceinline__ float lg2f_(float x){ float y; asm("lg2.approx.f32 %0, %1;":"=f"(y):"f"(x)); return y; }
__device__ __forceinline__ float tanhf_(float x){ float y; asm("tanh.approx.f32 %0, %1;":"=f"(y):"f"(x)); return y; }

#define LOG2E 1.4426950408889634f
#define C2COEF 6.931471805599453e-4f        /* dt*ln2 */
#define INVC   1442.6950408889634f          /* 1/(dt*ln2) */

// ---------------- K1: precompute + transpose ----------------
__global__ void __launch_bounds__(256) lugre_pre(
    const float* __restrict__ x,        // [B, T, 3]: v, F_c, F_s
    const float* __restrict__ alpha,
    const float* __restrict__ vs)
{
    __shared__ float4 tile[32][33];
    const int t0 = blockIdx.x * 32;
    const int b0 = blockIdx.y * 32;
    const float a0  = alpha[0];
    const float lvs = lg2f_(fabsf(vs[0]));
    const int tx = threadIdx.x, ty = threadIdx.y;

    #pragma unroll
    for (int i = 0; i < 4; i++) {
        int bl = ty + 8 * i;
        size_t base = ((size_t)(b0 + bl) * TT + (t0 + tx)) * 3;
        float v  = x[base];
        float Fc = x[base + 1];
        float Fs = x[base + 2];
        float av = fabsf(v);
        float p  = ex2f_(a0 * (lg2f_(av) - lvs));   // |v/vs|^alpha
        float w  = ex2f_(-LOG2E * p);               // exp(-p)
        float g  = fmaf(Fs - Fc, w, Fc);
        float sg = (v > 0.f) ? 1.f : ((v < 0.f) ? -1.f : 0.f);
        float k  = g * sg;
        float c2 = __fdividef(av, g) * C2COEF;      // dt*ln2*|v|/g
        tile[bl][tx] = make_float4(v, k, c2, Fs);
    }
    __syncthreads();
    #pragma unroll
    for (int i = 0; i < 4; i++) {
        int tl = ty + 8 * i;
        g_pre[(size_t)(t0 + tl) * BB + (b0 + tx)] = tile[tx][tl];
    }
}

// ---------------- K2: build scalar table ----------------
__global__ void __launch_bounds__(256) lugre_tab(
    const float* __restrict__ W1, const float* __restrict__ b1,
    const float* __restrict__ W2, const float* __restrict__ b2)
{
    int idx = blockIdx.x * blockDim.x + threadIdx.x;
    if (idx >= (NVC + 1) * (NSC + 1)) return;
    int iv = idx / (NSC + 1);
    int is = idx - iv * (NSC + 1);
    float v  = VMIN  + (float)iv * DV;
    float sz = SZMIN + (float)is * DSZ;
    float y0 = 0.f, y1 = 0.f;
    #pragma unroll 8
    for (int j = 0; j < HH; j++) {
        float z = fmaf(v, __ldg(W1 + j), fmaf(sz, __ldg(W1 + HH + j), __ldg(b1 + j)));
        float h = tanhf_(z);
        if (j & 1) y1 = fmaf(h, __ldg(W2 + j), y1);
        else       y0 = fmaf(h, __ldg(W2 + j), y0);
    }
    float ys = (y0 + y1 + __ldg(b2)) * LOG2E;
    g_Ls[idx] = lg2f_(1.0f + ex2f_(ys));            // sp(y)*log2e
}

// ---------------- K3: pack quads ----------------
__global__ void __launch_bounds__(256) lugre_pack()
{
    int idx = blockIdx.x * blockDim.x + threadIdx.x;
    if (idx >= NVC * NSC) return;
    int iv = idx >> 9;          // /NSC
    int is = idx & (NSC - 1);
    int base = iv * (NSC + 1) + is;
    float l00 = g_Ls[base];
    float l01 = g_Ls[base + 1];
    float l10 = g_Ls[base + NSC + 1];
    float l11 = g_Ls[base + NSC + 2];
    g_tab4[idx] = make_float4(l00, l01, l10, l11);
}

// ---------------- K4: sequential scan ----------------
// Build linearized update for target step (v,k,c2 in t8) at pred:
//   szn(S) ~= ca + cb*S   (exact at S=pred, 1st order around it)
__device__ __forceinline__ void refill(
    float4 t8, float pred, float& ca, float& cb)
{
    float fv  = fmaf(t8.x, INV_DV, OFF_V);
    int   iv  = (int)floorf(fv);
    iv = max(0, min(iv, NVC - 1));
    float frv = fminf(fmaxf(fv - (float)iv, 0.f), 1.f);
    float fs  = fmaf(pred, INV_DSZ, OFF_S);
    int   is  = (int)floorf(fs);
    is = max(0, min(is, NSC - 1));
    float frs = fminf(fmaxf(fs - (float)is, 0.f), 1.f);
    float4 q = __ldg(&g_tab4[((size_t)iv << 9) + is]);  // l00,l01,l10,l11
    float a_  = fmaf(frv, q.z - q.x, q.x);
    float b_  = fmaf(frv, q.w - q.y, q.y);
    float Lg0 = fmaf(frs, b_ - a_, a_);                 // sp(y)*log2e at (v,pred)
    float qs  = (b_ - a_) * INV_DSZ;                    // dLg/dsz
    float u0  = t8.z * Lg0;                             // dt*sig0*|v|/g
    float m0  = u0 * fmaf(u0, fmaf(u0, 0.16666667f, -0.5f), 1.f); // 1-exp(-u0)
    float mp  = fmaf(u0, fmaf(u0, 0.5f, -1.f), 1.f);    // dm/du at u0
    float dmdS = (t8.z * qs) * mp;                      // dm/dS
    float pk_ = pred - t8.y;                            // pred - k
    cb = fmaf(-pk_, dmdS, 1.f - m0);
    float base = fmaf(-pk_, m0, pred);                  // szn at pred
    ca = fmaf(-cb, pred, base);
}

__global__ void __launch_bounds__(32) lugre_scan(
    const float* __restrict__ sg1, const float* __restrict__ sg2,
    float* __restrict__ out)
{
    const int lane = threadIdx.x;                 // one batch per lane
    const int b = blockIdx.x * 32 + lane;         // 128 blocks x 32
    const float s1 = fabsf(sg1[0]);
    const float s2 = fabsf(sg2[0]);

    const float4* __restrict__ p = g_pre + b;
    float* __restrict__ outp = out + (size_t)b * TT;

    // staged input blocks: cur = steps tb..tb+7, mid = +8, far = +16
    float4 cur[8], mid[8];
    #pragma unroll
    for (int s = 0; s < 8; s++) cur[s] = __ldg(p + (size_t)s * BB);
    #pragma unroll
    for (int s = 0; s < 8; s++) mid[s] = __ldg(p + (size_t)(8 + s) * BB);

    float S = 0.0f;
    float ca[8], cb[8];
    #pragma unroll
    for (int s = 0; s < 8; s++) refill(cur[s], 0.0f, ca[s], cb[s]);  // pred=S_0=0

    float ff[4];

    for (int tb = 0; tb < TT; tb += 8) {
        // prefetch block tb+16 (clamped; stale tail values feed unused slots)
        int tf = tb + 16;
        if (tf > TT - 8) tf = TT - 8;
        float4 far[8];
        #pragma unroll
        for (int s = 0; s < 8; s++) far[s] = __ldg(p + (size_t)(tf + s) * BB);

        #pragma unroll
        for (int s = 0; s < 8; s++) {
            float4 pk = cur[s];
            float pred = S;                          // S entering step tb+s
            // ---- critical chain: linearized update ----
            float szn = fmaf(cb[s], S, ca[s]);       // pre-clip sz_{i+1}
            float szc = fminf(fmaxf(szn, -pk.w), pk.w);
            // ---- off-chain outputs ----
            float zd  = fmaf(-szn, pk.z * INVC, pk.x);
            ff[s & 3] = fmaf(s1, zd, fmaf(s2, pk.x, szc));
            S = szc;
            // ---- off-chain refill for step tb+s+8 at pred ----
            refill(mid[s], pred, ca[s], cb[s]);
            if ((s & 3) == 3) {
                *reinterpret_cast<float4*>(outp + tb + (s - 3)) =
                    make_float4(ff[0], ff[1], ff[2], ff[3]);
            }
        }
        #pragma unroll
        for (int s = 0; s < 8; s++) { cur[s] = mid[s]; mid[s] = far[s]; }
    }
}

// ---------------- launch ----------------
extern "C" void kernel_launch(void* const* d_in, const int* in_sizes, int n_in,
                              void* d_out, int out_size) {
    const float* x     = (const float*)d_in[0];
    const float* sig1  = (const float*)d_in[1];
    const float* sig2  = (const float*)d_in[2];
    const float* alpha = (const float*)d_in[3];
    const float* vs    = (const float*)d_in[4];
    const float* W1    = (const float*)d_in[5];
    const float* b1    = (const float*)d_in[6];
    const float* W2    = (const float*)d_in[7];
    const float* b2    = (const float*)d_in[8];
    float* out = (float*)d_out;

    dim3 blk(32, 8);
    dim3 grd(TT / 32, BB / 32);
    lugre_pre<<<grd, blk>>>(x, alpha, vs);

    int ntab = (NVC + 1) * (NSC + 1);
    lugre_tab<<<(ntab + 255) / 256, 256>>>(W1, b1, W2, b2);
    lugre_pack<<<(NVC * NSC) / 256, 256>>>();

    lugre_scan<<<128, 32>>>(sig1, sig2, out);
}

// round 10
// speedup vs baseline: 2.4640x; 2.4640x over previous
#include <cuda_runtime.h>
#include <cuda_bf16.h>
#include <cstdint>

// LuGreCell: B=4096, T=2048, S=1, H=64.
// K1 lugre_pre : per (b,t) v,k,c2,Fs -> time-major [T][B] float4.
// K2 lugre_tab : tabulate Lg(v,sz)=softplus(MLP(v,sz))*log2e on 2049x513 grid.
// K3 lugre_pack: pack bilinear quads into float4 cells.
// K4 lugre_scan: 128 warps (1/SM), 32 batches/warp (one per lane).
//   SPLIT-PHASE GATHER: for step i+16, the table LDG is ISSUED at step i
//   (address from S_i, v_{i+16}) and CONSUMED at step i+8 to build the
//   linearized update szn = ca + cb*S. Gather has ~8 steps (300+ cyc) in
//   flight -> L2 latency hidden despite 1 warp/SMSP. Chain: fma+clamp.

#define BB 4096
#define TT 2048
#define HH 64

// table geometry
#define NVC 2048
#define NSC 512
#define VMIN   (-8.0f)
#define DV     (16.0f / 2048.0f)
#define INV_DV 128.0f
#define OFF_V  1024.0f
#define SZMIN  (-2.6f)
#define DSZ    (5.2f / 512.0f)
#define INV_DSZ 98.46153846153847f
#define OFF_S  256.0f

__device__ float4 g_pre[(size_t)BB * TT];            // 134 MB scratch
__device__ float  g_Ls[(NVC + 1) * (NSC + 1)];       // 4.2 MB scalar table
__device__ float4 g_tab4[(size_t)NVC * NSC];         // 16.8 MB packed quads

__device__ __forceinline__ float ex2f_(float x){ float y; asm("ex2.approx.f32 %0, %1;":"=f"(y):"f"(x)); return y; }
__device__ __forceinline__ float lg2f_(float x){ float y; asm("lg2.approx.f32 %0, %1;":"=f"(y):"f"(x)); return y; }
__device__ __forceinline__ float tanhf_(float x){ float y; asm("tanh.approx.f32 %0, %1;":"=f"(y):"f"(x)); return y; }

#define LOG2E 1.4426950408889634f
#define C2COEF 6.931471805599453e-4f        /* dt*ln2 */
#define INVC   1442.6950408889634f          /* 1/(dt*ln2) */

// ---------------- K1: precompute + transpose ----------------
__global__ void __launch_bounds__(256) lugre_pre(
    const float* __restrict__ x,
    const float* __restrict__ alpha,
    const float* __restrict__ vs)
{
    __shared__ float4 tile[32][33];
    const int t0 = blockIdx.x * 32;
    const int b0 = blockIdx.y * 32;
    const float a0  = alpha[0];
    const float lvs = lg2f_(fabsf(vs[0]));
    const int tx = threadIdx.x, ty = threadIdx.y;

    #pragma unroll
    for (int i = 0; i < 4; i++) {
        int bl = ty + 8 * i;
        size_t base = ((size_t)(b0 + bl) * TT + (t0 + tx)) * 3;
        float v  = x[base];
        float Fc = x[base + 1];
        float Fs = x[base + 2];
        float av = fabsf(v);
        float p  = ex2f_(a0 * (lg2f_(av) - lvs));
        float w  = ex2f_(-LOG2E * p);
        float g  = fmaf(Fs - Fc, w, Fc);
        float sg = (v > 0.f) ? 1.f : ((v < 0.f) ? -1.f : 0.f);
        float k  = g * sg;
        float c2 = __fdividef(av, g) * C2COEF;
        tile[bl][tx] = make_float4(v, k, c2, Fs);
    }
    __syncthreads();
    #pragma unroll
    for (int i = 0; i < 4; i++) {
        int tl = ty + 8 * i;
        g_pre[(size_t)(t0 + tl) * BB + (b0 + tx)] = tile[tx][tl];
    }
}

// ---------------- K2: build scalar table ----------------
__global__ void __launch_bounds__(256) lugre_tab(
    const float* __restrict__ W1, const float* __restrict__ b1,
    const float* __restrict__ W2, const float* __restrict__ b2)
{
    int idx = blockIdx.x * blockDim.x + threadIdx.x;
    if (idx >= (NVC + 1) * (NSC + 1)) return;
    int iv = idx / (NSC + 1);
    int is = idx - iv * (NSC + 1);
    float v  = VMIN  + (float)iv * DV;
    float sz = SZMIN + (float)is * DSZ;
    float y0 = 0.f, y1 = 0.f;
    #pragma unroll 8
    for (int j = 0; j < HH; j++) {
        float z = fmaf(v, __ldg(W1 + j), fmaf(sz, __ldg(W1 + HH + j), __ldg(b1 + j)));
        float h = tanhf_(z);
        if (j & 1) y1 = fmaf(h, __ldg(W2 + j), y1);
        else       y0 = fmaf(h, __ldg(W2 + j), y0);
    }
    float ys = (y0 + y1 + __ldg(b2)) * LOG2E;
    g_Ls[idx] = lg2f_(1.0f + ex2f_(ys));
}

// ---------------- K3: pack quads ----------------
__global__ void __launch_bounds__(256) lugre_pack()
{
    int idx = blockIdx.x * blockDim.x + threadIdx.x;
    if (idx >= NVC * NSC) return;
    int iv = idx >> 9;
    int is = idx & (NSC - 1);
    int base = iv * (NSC + 1) + is;
    g_tab4[idx] = make_float4(g_Ls[base], g_Ls[base + 1],
                              g_Ls[base + NSC + 1], g_Ls[base + NSC + 2]);
}

// ---------------- K4: sequential scan ----------------
// addr-phase: from (v_target, pred) -> gather quad + fractions.
__device__ __forceinline__ void addr_phase(
    float vtgt, float pred,
    float4& q, float& frv, float& frs, float& qpred)
{
    float fv  = fmaf(vtgt, INV_DV, OFF_V);
    int   iv  = (int)floorf(fv);
    iv = max(0, min(iv, NVC - 1));
    frv = fminf(fmaxf(fv - (float)iv, 0.f), 1.f);
    float fs  = fmaf(pred, INV_DSZ, OFF_S);
    int   is  = (int)floorf(fs);
    is = max(0, min(is, NSC - 1));
    frs = fminf(fmaxf(fs - (float)is, 0.f), 1.f);
    q = __ldg(&g_tab4[((size_t)iv << 9) + is]);
    qpred = pred;
}

// build-phase: quad + tuple -> linearized update szn(S) ~ ca + cb*S.
__device__ __forceinline__ void build_phase(
    float4 t8, float4 q, float frv, float frs, float qpred,
    float& ca, float& cb)
{
    float a_  = fmaf(frv, q.z - q.x, q.x);
    float b_  = fmaf(frv, q.w - q.y, q.y);
    float Lg0 = fmaf(frs, b_ - a_, a_);
    float qs  = (b_ - a_) * INV_DSZ;
    float u0  = t8.z * Lg0;
    float m0  = u0 * fmaf(u0, fmaf(u0, 0.16666667f, -0.5f), 1.f);
    float mp  = fmaf(u0, fmaf(u0, 0.5f, -1.f), 1.f);
    float dmdS = (t8.z * qs) * mp;
    float pk_ = qpred - t8.y;
    cb = fmaf(-pk_, dmdS, 1.f - m0);
    ca = fmaf(-cb, qpred, fmaf(-pk_, m0, qpred));
}

__global__ void __launch_bounds__(32) lugre_scan(
    const float* __restrict__ sg1, const float* __restrict__ sg2,
    float* __restrict__ out)
{
    const int lane = threadIdx.x;
    const int b = blockIdx.x * 32 + lane;
    const float s1 = fabsf(sg1[0]);
    const float s2 = fabsf(sg2[0]);

    const float4* __restrict__ p = g_pre + b;
    const float*  __restrict__ pv = (const float*)(g_pre + b);   // .x of tuples
    float* __restrict__ outp = out + (size_t)b * TT;

    // full-tuple stages: cur = block tb, mid = tb+8, minf = in flight tb+16
    float4 cur[8], mid[8], minf[8];
    #pragma unroll
    for (int s = 0; s < 8; s++) cur[s]  = __ldg(p + (size_t)s * BB);
    #pragma unroll
    for (int s = 0; s < 8; s++) mid[s]  = __ldg(p + (size_t)(8 + s) * BB);
    #pragma unroll
    for (int s = 0; s < 8; s++) minf[s] = __ldg(p + (size_t)(16 + s) * BB);
    // scalar-v stages for addressing: vfar = tb+16, vinf = tb+24
    float vfar[8], vinf[8];
    #pragma unroll
    for (int s = 0; s < 8; s++) vfar[s] = __ldg(pv + (size_t)(16 + s) * BB * 4);
    #pragma unroll
    for (int s = 0; s < 8; s++) vinf[s] = __ldg(pv + (size_t)(24 + s) * BB * 4);

    float S = 0.0f;
    float ca[8], cb[8], qpred[8], frv[8], frs[8];
    float4 q[8];

    // Prologue: exact builds for steps 0..7 at pred = S_0 = 0.
    #pragma unroll
    for (int s = 0; s < 8; s++) {
        float4 qq; float fv_, fs_, qp_;
        addr_phase(cur[s].x, 0.0f, qq, fv_, fs_, qp_);
        build_phase(cur[s], qq, fv_, fs_, qp_, ca[s], cb[s]);
    }
    // Gathers for steps 8..15, addressed at pred = 0.
    #pragma unroll
    for (int s = 0; s < 8; s++)
        addr_phase(mid[s].x, 0.0f, q[s], frv[s], frs[s], qpred[s]);

    float ff[4];

    for (int tb = 0; tb < TT; tb += 8) {
        #pragma unroll
        for (int s = 0; s < 8; s++) {
            // 1) build (ca,cb) for step tb+8+s from the in-flight quad
            float caN, cbN;
            build_phase(mid[s], q[s], frv[s], frs[s], qpred[s], caN, cbN);
            // 2) critical chain for step tb+s
            float4 pk = cur[s];
            float szn = fmaf(cb[s], S, ca[s]);
            float szc = fminf(fmaxf(szn, -pk.w), pk.w);
            float zd  = fmaf(-szn, pk.z * INVC, pk.x);
            ff[s & 3] = fmaf(s1, zd, fmaf(s2, pk.x, szc));
            S = szc;
            ca[s] = caN; cb[s] = cbN;
            // 3) issue gather for step tb+16+s, centered at latest S
            addr_phase(vfar[s], S, q[s], frv[s], frs[s], qpred[s]);
            if ((s & 3) == 3)
                *reinterpret_cast<float4*>(outp + tb + (s - 3)) =
                    make_float4(ff[0], ff[1], ff[2], ff[3]);
        }
        // rotate stages; issue next loads (clamped near the tail)
        int tm = tb + 24 <= TT - 8 ? tb + 24 : TT - 8;   // minf -> block tb+24
        int tv = tb + 32 <= TT - 8 ? tb + 32 : TT - 8;   // vinf -> block tb+32
        #pragma unroll
        for (int s = 0; s < 8; s++) {
            cur[s] = mid[s];
            mid[s] = minf[s];
            minf[s] = __ldg(p + (size_t)(tm + s) * BB);
            vfar[s] = vinf[s];
            vinf[s] = __ldg(pv + (size_t)(tv + s) * BB * 4);
        }
    }
}

// ---------------- launch ----------------
extern "C" void kernel_launch(void* const* d_in, const int* in_sizes, int n_in,
                              void* d_out, int out_size) {
    const float* x     = (const float*)d_in[0];
    const float* sig1  = (const float*)d_in[1];
    const float* sig2  = (const float*)d_in[2];
    const float* alpha = (const float*)d_in[3];
    const float* vs    = (const float*)d_in[4];
    const float* W1    = (const float*)d_in[5];
    const float* b1    = (const float*)d_in[6];
    const float* W2    = (const float*)d_in[7];
    const float* b2    = (const float*)d_in[8];
    float* out = (float*)d_out;

    dim3 blk(32, 8);
    dim3 grd(TT / 32, BB / 32);
    lugre_pre<<<grd, blk>>>(x, alpha, vs);

    int ntab = (NVC + 1) * (NSC + 1);
    lugre_tab<<<(ntab + 255) / 256, 256>>>(W1, b1, W2, b2);
    lugre_pack<<<(NVC * NSC) / 256, 256>>>();

    lugre_scan<<<128, 32>>>(sig1, sig2, out);
}

// round 11
// speedup vs baseline: 2.4786x; 1.0059x over previous
#include <cuda_runtime.h>
#include <cuda_bf16.h>
#include <cstdint>

// LuGreCell: B=4096, T=2048, S=1, H=64.
// K1 lugre_pre : per (b,t) v,k,c2,Fs -> time-major [T][B] float4.
// K2 lugre_tab : tabulate Lg(v,sz)=softplus(MLP(v,sz))*log2e (2049x513).
// K3 lugre_pack: pack bilinear quads into float4 cells.
// K4 lugre_scan: WARP-SPECIALIZED. 128 blocks x 128 thr; 32 batches/block
//   (one per lane). Warp 0 = chain warp: per step, 2 LDS + fma + clamp +
//   2-op F — nothing else. Warps 1-3 = helpers: build the per-step record
//   (ca,cb,e0,e1,Fs) one 8-step iteration ahead in double-buffered smem,
//   with split-phase table gathers (1 iter in flight, pred staleness 24).
//   One __syncthreads per 8 steps.

#define BB 4096
#define TT 2048
#define HH 64

#define NVC 2048
#define NSC 512
#define VMIN   (-8.0f)
#define DV     (16.0f / 2048.0f)
#define INV_DV 128.0f
#define OFF_V  1024.0f
#define SZMIN  (-2.6f)
#define DSZ    (5.2f / 512.0f)
#define INV_DSZ 98.46153846153847f
#define OFF_S  256.0f

__device__ float4 g_pre[(size_t)BB * TT];            // 134 MB scratch
__device__ float  g_Ls[(NVC + 1) * (NSC + 1)];       // 4.2 MB scalar table
__device__ float4 g_tab4[(size_t)NVC * NSC];         // 16.8 MB packed quads

__device__ __forceinline__ float ex2f_(float x){ float y; asm("ex2.approx.f32 %0, %1;":"=f"(y):"f"(x)); return y; }
__device__ __forceinline__ float lg2f_(float x){ float y; asm("lg2.approx.f32 %0, %1;":"=f"(y):"f"(x)); return y; }
__device__ __forceinline__ float tanhf_(float x){ float y; asm("tanh.approx.f32 %0, %1;":"=f"(y):"f"(x)); return y; }

#define LOG2E 1.4426950408889634f
#define C2COEF 6.931471805599453e-4f        /* dt*ln2 */
#define INVC   1442.6950408889634f          /* 1/(dt*ln2) */

// ---------------- K1: precompute + transpose ----------------
__global__ void __launch_bounds__(256) lugre_pre(
    const float* __restrict__ x,
    const float* __restrict__ alpha,
    const float* __restrict__ vs)
{
    __shared__ float4 tile[32][33];
    const int t0 = blockIdx.x * 32;
    const int b0 = blockIdx.y * 32;
    const float a0  = alpha[0];
    const float lvs = lg2f_(fabsf(vs[0]));
    const int tx = threadIdx.x, ty = threadIdx.y;

    #pragma unroll
    for (int i = 0; i < 4; i++) {
        int bl = ty + 8 * i;
        size_t base = ((size_t)(b0 + bl) * TT + (t0 + tx)) * 3;
        float v  = x[base];
        float Fc = x[base + 1];
        float Fs = x[base + 2];
        float av = fabsf(v);
        float p  = ex2f_(a0 * (lg2f_(av) - lvs));
        float w  = ex2f_(-LOG2E * p);
        float g  = fmaf(Fs - Fc, w, Fc);
        float sg = (v > 0.f) ? 1.f : ((v < 0.f) ? -1.f : 0.f);
        float k  = g * sg;
        float c2 = __fdividef(av, g) * C2COEF;
        tile[bl][tx] = make_float4(v, k, c2, Fs);
    }
    __syncthreads();
    #pragma unroll
    for (int i = 0; i < 4; i++) {
        int tl = ty + 8 * i;
        g_pre[(size_t)(t0 + tl) * BB + (b0 + tx)] = tile[tx][tl];
    }
}

// ---------------- K2: build scalar table ----------------
__global__ void __launch_bounds__(256) lugre_tab(
    const float* __restrict__ W1, const float* __restrict__ b1,
    const float* __restrict__ W2, const float* __restrict__ b2)
{
    int idx = blockIdx.x * blockDim.x + threadIdx.x;
    if (idx >= (NVC + 1) * (NSC + 1)) return;
    int iv = idx / (NSC + 1);
    int is = idx - iv * (NSC + 1);
    float v  = VMIN  + (float)iv * DV;
    float sz = SZMIN + (float)is * DSZ;
    float y0 = 0.f, y1 = 0.f;
    #pragma unroll 8
    for (int j = 0; j < HH; j++) {
        float z = fmaf(v, __ldg(W1 + j), fmaf(sz, __ldg(W1 + HH + j), __ldg(b1 + j)));
        float h = tanhf_(z);
        if (j & 1) y1 = fmaf(h, __ldg(W2 + j), y1);
        else       y0 = fmaf(h, __ldg(W2 + j), y0);
    }
    float ys = (y0 + y1 + __ldg(b2)) * LOG2E;
    g_Ls[idx] = lg2f_(1.0f + ex2f_(ys));
}

// ---------------- K3: pack quads ----------------
__global__ void __launch_bounds__(256) lugre_pack()
{
    int idx = blockIdx.x * blockDim.x + threadIdx.x;
    if (idx >= NVC * NSC) return;
    int iv = idx >> 9;
    int is = idx & (NSC - 1);
    int base = iv * (NSC + 1) + is;
    g_tab4[idx] = make_float4(g_Ls[base], g_Ls[base + 1],
                              g_Ls[base + NSC + 1], g_Ls[base + NSC + 2]);
}

// ---------------- K4: warp-specialized scan ----------------
__device__ __forceinline__ void addr_phase(
    float vtgt, float pred,
    float4& q, float& frv, float& frs, float& qpred)
{
    float fv  = fmaf(vtgt, INV_DV, OFF_V);
    int   iv  = (int)floorf(fv);
    iv = max(0, min(iv, NVC - 1));
    frv = fminf(fmaxf(fv - (float)iv, 0.f), 1.f);
    float fs  = fmaf(pred, INV_DSZ, OFF_S);
    int   is  = (int)floorf(fs);
    is = max(0, min(is, NSC - 1));
    frs = fminf(fmaxf(fs - (float)is, 0.f), 1.f);
    q = __ldg(&g_tab4[((size_t)iv << 9) + is]);
    qpred = pred;
}

__device__ __forceinline__ void build_phase(
    float4 t8, float4 q, float frv, float frs, float qpred,
    float& ca, float& cb)
{
    float a_  = fmaf(frv, q.z - q.x, q.x);
    float b_  = fmaf(frv, q.w - q.y, q.y);
    float Lg0 = fmaf(frs, b_ - a_, a_);
    float qs  = (b_ - a_) * INV_DSZ;
    float u0  = t8.z * Lg0;
    float m0  = u0 * fmaf(u0, fmaf(u0, 0.16666667f, -0.5f), 1.f);
    float mp  = fmaf(u0, fmaf(u0, 0.5f, -1.f), 1.f);
    float dmdS = (t8.z * qs) * mp;
    float pk_ = qpred - t8.y;
    cb = fmaf(-pk_, dmdS, 1.f - m0);
    ca = fmaf(-cb, qpred, fmaf(-pk_, m0, qpred));
}

__global__ void __launch_bounds__(128) lugre_scan(
    const float* __restrict__ sg1, const float* __restrict__ sg2,
    float* __restrict__ out)
{
    __shared__ float4 cab4[2][8][32];   // (ca, cb, e0, e1)
    __shared__ float  cfs [2][8][32];   // Fs
    __shared__ float  sring[2][8][32];  // S after each step

    const int lane = threadIdx.x & 31;
    const int wid  = threadIdx.x >> 5;        // 0 chain, 1..3 helpers
    const int b    = blockIdx.x * 32 + lane;
    const float s1 = fabsf(sg1[0]);
    const float s2 = fabsf(sg2[0]);
    const float s12 = s1 + s2;

    const float4* __restrict__ p = g_pre + b;
    float* __restrict__ outp = out + (size_t)b * TT;

    // ---------------- prologue ----------------
    if (wid > 0) {
        const int ns = (wid == 3) ? 2 : 3;
        const int s0 = (wid - 1) * 3;
        // zero sring parity 1 (read by helpers at n=0 as S_{-1}=0)
        for (int j = 0; j < ns; j++) sring[1][s0 + j][lane] = 0.0f;
        for (int j = 0; j < ns; j++) {
            int s = s0 + j;
            // C_0 exact at pred=0 (block 0)
            float4 t0 = __ldg(p + (size_t)s * BB);
            float4 q0; float fv0, fs0, qp0, ca, cb;
            addr_phase(t0.x, 0.0f, q0, fv0, fs0, qp0);
            build_phase(t0, q0, fv0, fs0, qp0, ca, cb);
            cab4[0][s][lane] = make_float4(ca, cb, s12 * t0.x, s1 * t0.z * INVC);
            cfs [0][s][lane] = t0.w;
        }
    }

    // helper persistent state
    float4 tupA[3], tupB[3], qA[3];
    float frvA[3], frsA[3], qpA[3];
    if (wid > 0) {
        const int ns = (wid == 3) ? 2 : 3;
        const int s0 = (wid - 1) * 3;
        for (int j = 0; j < ns; j++) {
            int s = s0 + j;
            tupA[j] = __ldg(p + (size_t)(8 + s) * BB);    // block 1 (C_1 target)
            addr_phase(tupA[j].x, 0.0f, qA[j], frvA[j], frsA[j], qpA[j]); // gather C_1
            tupB[j] = __ldg(p + (size_t)(16 + s) * BB);   // block 2 (addr C_2)
        }
    }
    __syncthreads();

    // ---------------- main loop: 256 iterations of 8 steps ----------------
    float S = 0.0f;
    float ff[4];

    for (int n = 0; n < TT / 8; n++) {
        if (wid == 0) {
            // chain warp: consume records parity n&1
            const int pr = n & 1;
            float4 cc[8]; float fsv[8];
            #pragma unroll
            for (int s = 0; s < 8; s++) { cc[s] = cab4[pr][s][lane]; fsv[s] = cfs[pr][s][lane]; }
            const int tb = n * 8;
            #pragma unroll
            for (int s = 0; s < 8; s++) {
                float szn = fmaf(cc[s].y, S, cc[s].x);
                float szc = fminf(fmaxf(szn, -fsv[s]), fsv[s]);
                float F   = fmaf(-cc[s].w, szn, cc[s].z) + szc;
                sring[pr][s][lane] = szc;
                S = szc;
                ff[s & 3] = F;
                if ((s & 3) == 3)
                    *reinterpret_cast<float4*>(outp + tb + (s - 3)) =
                        make_float4(ff[0], ff[1], ff[2], ff[3]);
            }
        } else {
            // helpers: build C_{n+1}, issue gathers for C_{n+2}, stage tuples
            const int ns = (wid == 3) ? 2 : 3;
            const int s0 = (wid - 1) * 3;
            const int pw = (n + 1) & 1;
            #pragma unroll
            for (int j = 0; j < 3; j++) {
                if (j >= ns) break;
                int s = s0 + j;
                float ca, cb;
                build_phase(tupA[j], qA[j], frvA[j], frsA[j], qpA[j], ca, cb);
                cab4[pw][s][lane] =
                    make_float4(ca, cb, s12 * tupA[j].x, s1 * tupA[j].z * INVC);
                cfs [pw][s][lane] = tupA[j].w;
                // gather for C_{n+2}: v from block n+2 (tupB), pred = S_{8(n-1)+s}
                float Sp = sring[pw][s][lane];    // (n-1)&1 == (n+1)&1
                addr_phase(tupB[j].x, Sp, qA[j], frvA[j], frsA[j], qpA[j]);
                tupA[j] = tupB[j];
                int blk3 = n + 3 <= TT / 8 - 1 ? n + 3 : TT / 8 - 1;
                tupB[j] = __ldg(p + (size_t)(blk3 * 8 + s) * BB);
            }
        }
        __syncthreads();
    }
}

// ---------------- launch ----------------
extern "C" void kernel_launch(void* const* d_in, const int* in_sizes, int n_in,
                              void* d_out, int out_size) {
    const float* x     = (const float*)d_in[0];
    const float* sig1  = (const float*)d_in[1];
    const float* sig2  = (const float*)d_in[2];
    const float* alpha = (const float*)d_in[3];
    const float* vs    = (const float*)d_in[4];
    const float* W1    = (const float*)d_in[5];
    const float* b1    = (const float*)d_in[6];
    const float* W2    = (const float*)d_in[7];
    const float* b2    = (const float*)d_in[8];
    float* out = (float*)d_out;

    dim3 blk(32, 8);
    dim3 grd(TT / 32, BB / 32);
    lugre_pre<<<grd, blk>>>(x, alpha, vs);

    int ntab = (NVC + 1) * (NSC + 1);
    lugre_tab<<<(ntab + 255) / 256, 256>>>(W1, b1, W2, b2);
    lugre_pack<<<(NVC * NSC) / 256, 256>>>();

    lugre_scan<<<128, 128>>>(sig1, sig2, out);
}

// round 12
// speedup vs baseline: 2.7444x; 1.1072x over previous
#include <cuda_runtime.h>
#include <cuda_bf16.h>
#include <cstdint>

// LuGreCell: B=4096, T=2048, S=1, H=64.
// K1 lugre_pre : per (b,t) v,k,c2,Fs -> time-major [T][B] float4.
// K2 lugre_tab : tabulate Lg(v,sz)=softplus(MLP(v,sz))*log2e, 161x65 nodes.
// K3 lugre_pack: pack bilinear quads into float4 cells (160x64).
// K4 lugre_scan: warp-specialized; the WHOLE quad table lives in SMEM
//   (164KB), so helper gathers are LDS (no L1tex wavefront storm / L2
//   scatter). Warp 0 = chain (fma+clamp per step); warps 1-3 = helpers
//   build records (ca,cb,e0,e1,Fs) one 8-step iteration ahead.

#define BB 4096
#define TT 2048
#define HH 64

// small table geometry (SMEM-resident)
#define NV2 160
#define NS2 64
#define VMIN2   (-8.0f)
#define INV_DV2 10.0f
#define OFF_V2  80.0f
#define INV_DSZ2 12.307692307692308f   /* 64 / 5.2 */
#define OFF_S2  32.0f
#define DV2     0.1f
#define DSZ2    0.08125f
#define TAB_CELLS (NV2 * NS2)
#define TAB_BYTES (TAB_CELLS * 16)

__device__ float4 g_pre[(size_t)BB * TT];              // 134 MB scratch
__device__ float  g_Ls[(NV2 + 1) * (NS2 + 1)];         // scalar nodes
__device__ float4 g_tab4[TAB_CELLS];                   // packed quads

__device__ __forceinline__ float ex2f_(float x){ float y; asm("ex2.approx.f32 %0, %1;":"=f"(y):"f"(x)); return y; }
__device__ __forceinline__ float lg2f_(float x){ float y; asm("lg2.approx.f32 %0, %1;":"=f"(y):"f"(x)); return y; }
__device__ __forceinline__ float tanhf_(float x){ float y; asm("tanh.approx.f32 %0, %1;":"=f"(y):"f"(x)); return y; }

#define LOG2E 1.4426950408889634f
#define C2COEF 6.931471805599453e-4f        /* dt*ln2 */
#define INVC   1442.6950408889634f          /* 1/(dt*ln2) */

// ---------------- K1: precompute + transpose ----------------
__global__ void __launch_bounds__(256) lugre_pre(
    const float* __restrict__ x,
    const float* __restrict__ alpha,
    const float* __restrict__ vs)
{
    __shared__ float4 tile[32][33];
    const int t0 = blockIdx.x * 32;
    const int b0 = blockIdx.y * 32;
    const float a0  = alpha[0];
    const float lvs = lg2f_(fabsf(vs[0]));
    const int tx = threadIdx.x, ty = threadIdx.y;

    #pragma unroll
    for (int i = 0; i < 4; i++) {
        int bl = ty + 8 * i;
        size_t base = ((size_t)(b0 + bl) * TT + (t0 + tx)) * 3;
        float v  = x[base];
        float Fc = x[base + 1];
        float Fs = x[base + 2];
        float av = fabsf(v);
        float p  = ex2f_(a0 * (lg2f_(av) - lvs));
        float w  = ex2f_(-LOG2E * p);
        float g  = fmaf(Fs - Fc, w, Fc);
        float sg = (v > 0.f) ? 1.f : ((v < 0.f) ? -1.f : 0.f);
        float k  = g * sg;
        float c2 = __fdividef(av, g) * C2COEF;
        tile[bl][tx] = make_float4(v, k, c2, Fs);
    }
    __syncthreads();
    #pragma unroll
    for (int i = 0; i < 4; i++) {
        int tl = ty + 8 * i;
        g_pre[(size_t)(t0 + tl) * BB + (b0 + tx)] = tile[tx][tl];
    }
}

// ---------------- K2: build scalar node table ----------------
__global__ void __launch_bounds__(256) lugre_tab(
    const float* __restrict__ W1, const float* __restrict__ b1,
    const float* __restrict__ W2, const float* __restrict__ b2)
{
    int idx = blockIdx.x * blockDim.x + threadIdx.x;
    if (idx >= (NV2 + 1) * (NS2 + 1)) return;
    int iv = idx / (NS2 + 1);
    int is = idx - iv * (NS2 + 1);
    float v  = VMIN2 + (float)iv * DV2;
    float sz = -2.6f + (float)is * DSZ2;
    float y0 = 0.f, y1 = 0.f;
    #pragma unroll 8
    for (int j = 0; j < HH; j++) {
        float z = fmaf(v, __ldg(W1 + j), fmaf(sz, __ldg(W1 + HH + j), __ldg(b1 + j)));
        float h = tanhf_(z);
        if (j & 1) y1 = fmaf(h, __ldg(W2 + j), y1);
        else       y0 = fmaf(h, __ldg(W2 + j), y0);
    }
    float ys = (y0 + y1 + __ldg(b2)) * LOG2E;
    g_Ls[idx] = lg2f_(1.0f + ex2f_(ys));               // sp(y)*log2e
}

// ---------------- K3: pack quads ----------------
__global__ void __launch_bounds__(256) lugre_pack()
{
    int idx = blockIdx.x * blockDim.x + threadIdx.x;
    if (idx >= TAB_CELLS) return;
    int iv = idx / NS2;
    int is = idx - iv * NS2;
    int base = iv * (NS2 + 1) + is;
    g_tab4[idx] = make_float4(g_Ls[base], g_Ls[base + 1],
                              g_Ls[base + NS2 + 1], g_Ls[base + NS2 + 2]);
}

// ---------------- K4: warp-specialized scan ----------------
// One-shot refill: SMEM bilinear gather -> linearized update szn ~ ca+cb*S.
__device__ __forceinline__ void refill_smem(
    const float4* __restrict__ tab,
    float4 t8, float pred, float& ca, float& cb)
{
    float fv  = fmaf(t8.x, INV_DV2, OFF_V2);
    int   iv  = (int)floorf(fv);
    iv = max(0, min(iv, NV2 - 1));
    float frv = fminf(fmaxf(fv - (float)iv, 0.f), 1.f);
    float fs  = fmaf(pred, INV_DSZ2, OFF_S2);
    int   is  = (int)floorf(fs);
    is = max(0, min(is, NS2 - 1));
    float frs = fminf(fmaxf(fs - (float)is, 0.f), 1.f);
    float4 q = tab[iv * NS2 + is];      // LDS.128
    float a_  = fmaf(frv, q.z - q.x, q.x);
    float b_  = fmaf(frv, q.w - q.y, q.y);
    float Lg0 = fmaf(frs, b_ - a_, a_);
    float qs  = (b_ - a_) * INV_DSZ2;
    float u0  = t8.z * Lg0;
    float m0  = u0 * fmaf(u0, fmaf(u0, 0.16666667f, -0.5f), 1.f);
    float mp  = fmaf(u0, fmaf(u0, 0.5f, -1.f), 1.f);
    float dmdS = (t8.z * qs) * mp;
    float pk_ = pred - t8.y;
    cb = fmaf(-pk_, dmdS, 1.f - m0);
    ca = fmaf(-cb, pred, fmaf(-pk_, m0, pred));
}

__global__ void __launch_bounds__(128) lugre_scan(
    const float* __restrict__ sg1, const float* __restrict__ sg2,
    float* __restrict__ out)
{
    extern __shared__ float4 tab[];     // TAB_BYTES quad table
    __shared__ float4 cab4[2][8][32];   // (ca, cb, e0, e1)
    __shared__ float  cfs [2][8][32];   // Fs
    __shared__ float  sring[2][8][32];  // S after each step

    const int tid  = threadIdx.x;
    const int lane = tid & 31;
    const int wid  = tid >> 5;          // 0 chain, 1..3 helpers
    const int b    = blockIdx.x * 32 + lane;
    const float s1 = fabsf(sg1[0]);
    const float s2 = fabsf(sg2[0]);
    const float s12 = s1 + s2;

    const float4* __restrict__ p = g_pre + b;
    float* __restrict__ outp = out + (size_t)b * TT;

    // copy quad table into SMEM (all 128 threads)
    for (int i = tid; i < TAB_CELLS; i += 128) tab[i] = __ldg(&g_tab4[i]);
    __syncthreads();

    // ---------------- prologue ----------------
    float4 tupA[3], tupB[3];
    if (wid > 0) {
        const int ns = (wid == 3) ? 2 : 3;
        const int s0 = (wid - 1) * 3;
        for (int j = 0; j < ns; j++) {
            int s = s0 + j;
            sring[1][s][lane] = 0.0f;    // read at n=0 as stale pred
            // C_0 exact at pred=0 (block 0)
            float4 t0 = __ldg(p + (size_t)s * BB);
            float ca, cb;
            refill_smem(tab, t0, 0.0f, ca, cb);
            cab4[0][s][lane] = make_float4(ca, cb, s12 * t0.x, s1 * t0.z * INVC);
            cfs [0][s][lane] = t0.w;
            tupA[j] = __ldg(p + (size_t)(8 + s) * BB);    // block 1
            tupB[j] = __ldg(p + (size_t)(16 + s) * BB);   // block 2
        }
    }
    __syncthreads();

    // ---------------- main loop: TT/8 iterations of 8 steps ----------------
    float S = 0.0f;
    float ff[4];

    for (int n = 0; n < TT / 8; n++) {
        if (wid == 0) {
            const int pr = n & 1;
            float4 cc[8]; float fsv[8];
            #pragma unroll
            for (int s = 0; s < 8; s++) { cc[s] = cab4[pr][s][lane]; fsv[s] = cfs[pr][s][lane]; }
            const int tb = n * 8;
            #pragma unroll
            for (int s = 0; s < 8; s++) {
                float szn = fmaf(cc[s].y, S, cc[s].x);
                float szc = fminf(fmaxf(szn, -fsv[s]), fsv[s]);
                float F   = fmaf(-cc[s].w, szn, cc[s].z) + szc;
                sring[pr][s][lane] = szc;
                S = szc;
                ff[s & 3] = F;
                if ((s & 3) == 3)
                    *reinterpret_cast<float4*>(outp + tb + (s - 3)) =
                        make_float4(ff[0], ff[1], ff[2], ff[3]);
            }
        } else {
            // helpers: build C_{n+1} from tupA (block n+1) with pred from
            // iteration n-1 (same parity as write target), stage tuples.
            const int ns = (wid == 3) ? 2 : 3;
            const int s0 = (wid - 1) * 3;
            const int pw = (n + 1) & 1;
            #pragma unroll
            for (int j = 0; j < 3; j++) {
                if (j >= ns) break;
                int s = s0 + j;
                float Sp = sring[pw][s][lane];       // S_{8(n-1)+s}
                float ca, cb;
                refill_smem(tab, tupA[j], Sp, ca, cb);
                cab4[pw][s][lane] =
                    make_float4(ca, cb, s12 * tupA[j].x, s1 * tupA[j].z * INVC);
                cfs [pw][s][lane] = tupA[j].w;
                tupA[j] = tupB[j];
                int blk3 = n + 3 <= TT / 8 - 1 ? n + 3 : TT / 8 - 1;
                tupB[j] = __ldg(p + (size_t)(blk3 * 8 + s) * BB);
            }
        }
        __syncthreads();
    }
}

// ---------------- launch ----------------
extern "C" void kernel_launch(void* const* d_in, const int* in_sizes, int n_in,
                              void* d_out, int out_size) {
    const float* x     = (const float*)d_in[0];
    const float* sig1  = (const float*)d_in[1];
    const float* sig2  = (const float*)d_in[2];
    const float* alpha = (const float*)d_in[3];
    const float* vs    = (const float*)d_in[4];
    const float* W1    = (const float*)d_in[5];
    const float* b1    = (const float*)d_in[6];
    const float* W2    = (const float*)d_in[7];
    const float* b2    = (const float*)d_in[8];
    float* out = (float*)d_out;

    dim3 blk(32, 8);
    dim3 grd(TT / 32, BB / 32);
    lugre_pre<<<grd, blk>>>(x, alpha, vs);

    int ntab = (NV2 + 1) * (NS2 + 1);
    lugre_tab<<<(ntab + 255) / 256, 256>>>(W1, b1, W2, b2);
    lugre_pack<<<(TAB_CELLS + 255) / 256, 256>>>();

    static int smem_set = 0;
    if (!smem_set) {
        cudaFuncSetAttribute(lugre_scan,
            cudaFuncAttributeMaxDynamicSharedMemorySize, TAB_BYTES);
        smem_set = 1;
    }
    lugre_scan<<<128, 128, TAB_BYTES>>>(sig1, sig2, out);
}

// round 14
// speedup vs baseline: 3.0547x; 1.1131x over previous
#include <cuda_runtime.h>
#include <cuda_bf16.h>
#include <cstdint>

// LuGreCell: B=4096, T=2048, S=1, H=64.
// K2 lugre_tab : tabulate Lg(v,sz)=softplus(MLP(v,sz))*log2e, 161x65 nodes.
// K3 lugre_pack: pack bilinear quads into float4 cells (160x64).
// K4 lugre_scan: FUSED warp-specialized scan, 16 steps/iteration.
//   128 blocks x 128 thr; 32 batches/block (one per lane).
//   Warp 0 = chain: per step fma+clamp only (+off-path F), 1 barrier/16 steps.
//   Warps 1-3 = helpers: load raw x (v,Fc,Fs), do the old K1 precompute
//   inline (g,k,c2 via ex2/lg2), bilinear-gather the SMEM quad table and
//   emit linearized records (ca,cb,e0,e1,Fs) one 16-step iter ahead.

#define BB 4096
#define TT 2048
#define HH 64
#define NIT (TT / 16)

// SMEM-resident table geometry
#define NV2 160
#define NS2 64
#define VMIN2   (-8.0f)
#define INV_DV2 10.0f
#define OFF_V2  80.0f
#define INV_DSZ2 12.307692307692308f   /* 64 / 5.2 */
#define OFF_S2  32.0f
#define DV2     0.1f
#define DSZ2    0.08125f
#define TAB_CELLS (NV2 * NS2)
#define TAB_BYTES (TAB_CELLS * 16)

__device__ float  g_Ls[(NV2 + 1) * (NS2 + 1)];
__device__ float4 g_tab4[TAB_CELLS];

__device__ __forceinline__ float ex2f_(float x){ float y; asm("ex2.approx.f32 %0, %1;":"=f"(y):"f"(x)); return y; }
__device__ __forceinline__ float lg2f_(float x){ float y; asm("lg2.approx.f32 %0, %1;":"=f"(y):"f"(x)); return y; }
__device__ __forceinline__ float tanhf_(float x){ float y; asm("tanh.approx.f32 %0, %1;":"=f"(y):"f"(x)); return y; }

#define LOG2E 1.4426950408889634f
#define C2COEF 6.931471805599453e-4f        /* dt*ln2 */
#define INVC   1442.6950408889634f          /* 1/(dt*ln2) */

// ---------------- K2: build scalar node table ----------------
__global__ void __launch_bounds__(256) lugre_tab(
    const float* __restrict__ W1, const float* __restrict__ b1,
    const float* __restrict__ W2, const float* __restrict__ b2)
{
    int idx = blockIdx.x * blockDim.x + threadIdx.x;
    if (idx >= (NV2 + 1) * (NS2 + 1)) return;
    int iv = idx / (NS2 + 1);
    int is = idx - iv * (NS2 + 1);
    float v  = VMIN2 + (float)iv * DV2;
    float sz = -2.6f + (float)is * DSZ2;
    float y0 = 0.f, y1 = 0.f;
    #pragma unroll 8
    for (int j = 0; j < HH; j++) {
        float z = fmaf(v, __ldg(W1 + j), fmaf(sz, __ldg(W1 + HH + j), __ldg(b1 + j)));
        float h = tanhf_(z);
        if (j & 1) y1 = fmaf(h, __ldg(W2 + j), y1);
        else       y0 = fmaf(h, __ldg(W2 + j), y0);
    }
    float ys = (y0 + y1 + __ldg(b2)) * LOG2E;
    g_Ls[idx] = lg2f_(1.0f + ex2f_(ys));               // sp(y)*log2e
}

// ---------------- K3: pack quads ----------------
__global__ void __launch_bounds__(256) lugre_pack()
{
    int idx = blockIdx.x * blockDim.x + threadIdx.x;
    if (idx >= TAB_CELLS) return;
    int iv = idx / NS2;
    int is = idx - iv * NS2;
    int base = iv * (NS2 + 1) + is;
    g_tab4[idx] = make_float4(g_Ls[base], g_Ls[base + 1],
                              g_Ls[base + NS2 + 1], g_Ls[base + NS2 + 2]);
}

// ---------------- K4: fused warp-specialized scan ----------------
// Precompute (old K1) + table refill -> linearized record.
// GLOB=true reads quads from global (prologue, before smem table is ready).
template<bool GLOB>
__device__ __forceinline__ void make_record(
    const float4* __restrict__ tab,
    float v, float Fc, float Fs, float a0, float lvs, float pred,
    float& ca, float& cb, float& c2o)
{
    float av = fabsf(v);
    float pp = ex2f_(a0 * (lg2f_(av) - lvs));   // |v/vs|^alpha
    float w  = ex2f_(-LOG2E * pp);              // exp(-p)
    float g  = fmaf(Fs - Fc, w, Fc);
    float sg = (v > 0.f) ? 1.f : ((v < 0.f) ? -1.f : 0.f);
    float k  = g * sg;
    float c2 = __fdividef(av, g) * C2COEF;      // dt*ln2*|v|/g
    c2o = c2;
    // bilinear gather
    float fv  = fmaf(v, INV_DV2, OFF_V2);
    int   iv  = (int)floorf(fv);
    iv = max(0, min(iv, NV2 - 1));
    float frv = fminf(fmaxf(fv - (float)iv, 0.f), 1.f);
    float fs  = fmaf(pred, INV_DSZ2, OFF_S2);
    int   is  = (int)floorf(fs);
    is = max(0, min(is, NS2 - 1));
    float frs = fminf(fmaxf(fs - (float)is, 0.f), 1.f);
    float4 q = GLOB ? __ldg(&g_tab4[iv * NS2 + is]) : tab[iv * NS2 + is];
    float a_  = fmaf(frv, q.z - q.x, q.x);
    float b_  = fmaf(frv, q.w - q.y, q.y);
    float Lg0 = fmaf(frs, b_ - a_, a_);
    float qs  = (b_ - a_) * INV_DSZ2;
    float u0  = c2 * Lg0;
    float m0  = u0 * fmaf(u0, fmaf(u0, 0.16666667f, -0.5f), 1.f);
    float mp  = fmaf(u0, fmaf(u0, 0.5f, -1.f), 1.f);
    float dmdS = (c2 * qs) * mp;
    float pk_ = pred - k;
    cb = fmaf(-pk_, dmdS, 1.f - m0);
    ca = fmaf(-cb, pred, fmaf(-pk_, m0, pred));
}

__global__ void __launch_bounds__(128) lugre_scan(
    const float* __restrict__ x,
    const float* __restrict__ sg1, const float* __restrict__ sg2,
    const float* __restrict__ alpha, const float* __restrict__ vs,
    float* __restrict__ out)
{
    extern __shared__ float4 tab[];      // 160KB quad table
    __shared__ float4 cab4[2][16][32];   // (ca, cb, e0, e1)
    __shared__ float  cfs [2][16][32];   // Fs
    __shared__ float  sring[2][16][32];  // S after each step

    const int tid  = threadIdx.x;
    const int lane = tid & 31;
    const int wid  = tid >> 5;           // 0 chain, 1..3 helpers
    const int b    = blockIdx.x * 32 + lane;
    const float s1 = fabsf(sg1[0]);
    const float s2 = fabsf(sg2[0]);
    const float s12 = s1 + s2;

    float* __restrict__ outp = out + (size_t)b * TT;

    // copy quad table into SMEM
    for (int i = tid; i < TAB_CELLS; i += 128) tab[i] = __ldg(&g_tab4[i]);

    // helper slot assignment: w1: 0-5, w2: 6-10, w3: 11-15
    const int ns = (wid == 1) ? 6 : 5;
    const int s0 = (wid == 1) ? 0 : (wid == 2 ? 6 : 11);

    float va[6], fca[6], fsa[6];   // x for iter n+1
    float vb[6], fcb[6], fsb[6];   // x for iter n+2
    float a0 = 0.f, lvs = 0.f;

    if (wid > 0) {
        a0  = alpha[0];
        lvs = lg2f_(fabsf(vs[0]));
        const float* __restrict__ xp = x + (size_t)b * TT * 3;
        for (int j = 0; j < ns; j++) {
            int s = s0 + j;
            sring[1][s][lane] = 0.0f;    // stale pred for n=0 build
            // records for iter 0 at pred = 0 (step 0 exact); global quads
            size_t o0 = (size_t)s * 3;
            float v0 = __ldg(xp + o0), Fc0 = __ldg(xp + o0 + 1), Fs0 = __ldg(xp + o0 + 2);
            float ca, cb, c2v;
            make_record<true>(tab, v0, Fc0, Fs0, a0, lvs, 0.0f, ca, cb, c2v);
            cab4[0][s][lane] = make_float4(ca, cb, s12 * v0, s1 * c2v * INVC);
            cfs [0][s][lane] = Fs0;
            // stage x for iters 1 and 2
            size_t oA = (size_t)(16 + s) * 3;
            va[j] = __ldg(xp + oA); fca[j] = __ldg(xp + oA + 1); fsa[j] = __ldg(xp + oA + 2);
            size_t oB = (size_t)(32 + s) * 3;
            vb[j] = __ldg(xp + oB); fcb[j] = __ldg(xp + oB + 1); fsb[j] = __ldg(xp + oB + 2);
        }
    }
    __syncthreads();

    // ---------------- main loop: NIT iterations of 16 steps ----------------
    float S = 0.0f;
    float ff[4];

    for (int n = 0; n < NIT; n++) {
        if (wid == 0) {
            const int pr = n & 1;
            float4 cc[16]; float fsv[16];
            #pragma unroll
            for (int s = 0; s < 16; s++) {
                cc[s] = cab4[pr][s][lane];
                fsv[s] = cfs[pr][s][lane];
            }
            const int tb = n * 16;
            #pragma unroll
            for (int s = 0; s < 16; s++) {
                float szn = fmaf(cc[s].y, S, cc[s].x);
                float szc = fminf(fmaxf(szn, -fsv[s]), fsv[s]);
                float F   = fmaf(-cc[s].w, szn, cc[s].z) + szc;
                sring[pr][s][lane] = szc;
                S = szc;
                ff[s & 3] = F;
                if ((s & 3) == 3)
                    *reinterpret_cast<float4*>(outp + tb + (s - 3)) =
                        make_float4(ff[0], ff[1], ff[2], ff[3]);
            }
        } else {
            // build records for iter n+1 from staged x (va), pred from iter n-1
            const int pw = (n + 1) & 1;
            const float* __restrict__ xp = x + (size_t)b * TT * 3;
            #pragma unroll
            for (int j = 0; j < 6; j++) {
                if (j >= ns) break;
                int s = s0 + j;
                float Sp = sring[pw][s][lane];   // S_{16(n-1)+s}
                float ca, cb, c2v;
                make_record<false>(tab, va[j], fca[j], fsa[j], a0, lvs, Sp, ca, cb, c2v);
                cab4[pw][s][lane] =
                    make_float4(ca, cb, s12 * va[j], s1 * c2v * INVC);
                cfs [pw][s][lane] = fsa[j];
                // rotate x stages; load iter n+3 (clamped)
                va[j] = vb[j]; fca[j] = fcb[j]; fsa[j] = fsb[j];
                int nl = n + 3 <= NIT - 1 ? n + 3 : NIT - 1;
                size_t o = (size_t)(nl * 16 + s) * 3;
                vb[j] = __ldg(xp + o); fcb[j] = __ldg(xp + o + 1); fsb[j] = __ldg(xp + o + 2);
            }
        }
        __syncthreads();
    }
}

// ---------------- launch ----------------
extern "C" void kernel_launch(void* const* d_in, const int* in_sizes, int n_in,
                              void* d_out, int out_size) {
    const float* x     = (const float*)d_in[0];
    const float* sig1  = (const float*)d_in[1];
    const float* sig2  = (const float*)d_in[2];
    const float* alpha = (const float*)d_in[3];
    const float* vs    = (const float*)d_in[4];
    const float* W1    = (const float*)d_in[5];
    const float* b1    = (const float*)d_in[6];
    const float* W2    = (const float*)d_in[7];
    const float* b2    = (const float*)d_in[8];
    float* out = (float*)d_out;

    int ntab = (NV2 + 1) * (NS2 + 1);
    lugre_tab<<<(ntab + 255) / 256, 256>>>(W1, b1, W2, b2);
    lugre_pack<<<(TAB_CELLS + 255) / 256, 256>>>();

    // unconditional (no static guards — harness rules); idempotent host call
    cudaFuncSetAttribute(lugre_scan,
        cudaFuncAttributeMaxDynamicSharedMemorySize, TAB_BYTES);
    lugre_scan<<<128, 128, TAB_BYTES>>>(x, sig1, sig2, alpha, vs, out);
}

// round 15
// speedup vs baseline: 3.1055x; 1.0166x over previous
#include <cuda_runtime.h>
#include <cuda_bf16.h>
#include <cstdint>

// LuGreCell: B=4096, T=2048, S=1, H=64.
// K2 lugre_tab : tabulate Lg(v,sz)=softplus(MLP(v,sz))*log2e, 161x65 nodes.
// K3 lugre_pack: pack bilinear quads into float4 cells (160x64).
// K4 lugre_scan: fused warp-specialized scan, 16 steps/iteration.
//   Warp 0 = chain: rotating 4-record register window (LDS issued 4 steps
//   ahead of use -> no SMEM latency on the serial chain).
//   Warps 1-3 = helpers: COALESCED x staging through SMEM xbuf (float4
//   cooperative fill), inline K1 precompute + SMEM table gather, emit
//   linearized records (ca,cb,e0,e1,Fs) one iteration ahead.

#define BB 4096
#define TT 2048
#define HH 64
#define NIT (TT / 16)

// SMEM-resident table geometry
#define NV2 160
#define NS2 64
#define VMIN2   (-8.0f)
#define INV_DV2 10.0f
#define OFF_V2  80.0f
#define INV_DSZ2 12.307692307692308f   /* 64 / 5.2 */
#define OFF_S2  32.0f
#define DV2     0.1f
#define DSZ2    0.08125f
#define TAB_CELLS (NV2 * NS2)
#define TAB_BYTES (TAB_CELLS * 16)

#define XPAD 52   /* xbuf row stride in floats (16B-aligned, spreads banks) */

__device__ float  g_Ls[(NV2 + 1) * (NS2 + 1)];
__device__ float4 g_tab4[TAB_CELLS];

__device__ __forceinline__ float ex2f_(float x){ float y; asm("ex2.approx.f32 %0, %1;":"=f"(y):"f"(x)); return y; }
__device__ __forceinline__ float lg2f_(float x){ float y; asm("lg2.approx.f32 %0, %1;":"=f"(y):"f"(x)); return y; }
__device__ __forceinline__ float tanhf_(float x){ float y; asm("tanh.approx.f32 %0, %1;":"=f"(y):"f"(x)); return y; }

#define LOG2E 1.4426950408889634f
#define C2COEF 6.931471805599453e-4f        /* dt*ln2 */
#define INVC   1442.6950408889634f          /* 1/(dt*ln2) */

// ---------------- K2: build scalar node table ----------------
__global__ void __launch_bounds__(256) lugre_tab(
    const float* __restrict__ W1, const float* __restrict__ b1,
    const float* __restrict__ W2, const float* __restrict__ b2)
{
    int idx = blockIdx.x * blockDim.x + threadIdx.x;
    if (idx >= (NV2 + 1) * (NS2 + 1)) return;
    int iv = idx / (NS2 + 1);
    int is = idx - iv * (NS2 + 1);
    float v  = VMIN2 + (float)iv * DV2;
    float sz = -2.6f + (float)is * DSZ2;
    float y0 = 0.f, y1 = 0.f;
    #pragma unroll 8
    for (int j = 0; j < HH; j++) {
        float z = fmaf(v, __ldg(W1 + j), fmaf(sz, __ldg(W1 + HH + j), __ldg(b1 + j)));
        float h = tanhf_(z);
        if (j & 1) y1 = fmaf(h, __ldg(W2 + j), y1);
        else       y0 = fmaf(h, __ldg(W2 + j), y0);
    }
    float ys = (y0 + y1 + __ldg(b2)) * LOG2E;
    g_Ls[idx] = lg2f_(1.0f + ex2f_(ys));               // sp(y)*log2e
}

// ---------------- K3: pack quads ----------------
__global__ void __launch_bounds__(256) lugre_pack()
{
    int idx = blockIdx.x * blockDim.x + threadIdx.x;
    if (idx >= TAB_CELLS) return;
    int iv = idx / NS2;
    int is = idx - iv * NS2;
    int base = iv * (NS2 + 1) + is;
    g_tab4[idx] = make_float4(g_Ls[base], g_Ls[base + 1],
                              g_Ls[base + NS2 + 1], g_Ls[base + NS2 + 2]);
}

// ---------------- K4: fused warp-specialized scan ----------------
template<bool GLOB>
__device__ __forceinline__ void make_record(
    const float4* __restrict__ tab,
    float v, float Fc, float Fs, float a0, float lvs, float pred,
    float& ca, float& cb, float& c2o)
{
    float av = fabsf(v);
    float pp = ex2f_(a0 * (lg2f_(av) - lvs));   // |v/vs|^alpha
    float w  = ex2f_(-LOG2E * pp);              // exp(-p)
    float g  = fmaf(Fs - Fc, w, Fc);
    float sg = (v > 0.f) ? 1.f : ((v < 0.f) ? -1.f : 0.f);
    float k  = g * sg;
    float c2 = __fdividef(av, g) * C2COEF;      // dt*ln2*|v|/g
    c2o = c2;
    float fv  = fmaf(v, INV_DV2, OFF_V2);
    int   iv  = (int)floorf(fv);
    iv = max(0, min(iv, NV2 - 1));
    float frv = fminf(fmaxf(fv - (float)iv, 0.f), 1.f);
    float fs  = fmaf(pred, INV_DSZ2, OFF_S2);
    int   is  = (int)floorf(fs);
    is = max(0, min(is, NS2 - 1));
    float frs = fminf(fmaxf(fs - (float)is, 0.f), 1.f);
    float4 q = GLOB ? __ldg(&g_tab4[iv * NS2 + is]) : tab[iv * NS2 + is];
    float a_  = fmaf(frv, q.z - q.x, q.x);
    float b_  = fmaf(frv, q.w - q.y, q.y);
    float Lg0 = fmaf(frs, b_ - a_, a_);
    float qs  = (b_ - a_) * INV_DSZ2;
    float u0  = c2 * Lg0;
    float m0  = u0 * fmaf(u0, fmaf(u0, 0.16666667f, -0.5f), 1.f);
    float mp  = fmaf(u0, fmaf(u0, 0.5f, -1.f), 1.f);
    float dmdS = (c2 * qs) * mp;
    float pk_ = pred - k;
    cb = fmaf(-pk_, dmdS, 1.f - m0);
    ca = fmaf(-cb, pred, fmaf(-pk_, m0, pred));
}

__global__ void __launch_bounds__(128) lugre_scan(
    const float* __restrict__ x,
    const float* __restrict__ sg1, const float* __restrict__ sg2,
    const float* __restrict__ alpha, const float* __restrict__ vs,
    float* __restrict__ out)
{
    extern __shared__ float4 tab[];          // 160KB quad table
    __shared__ float4 cab4[2][16][32];       // (ca, cb, e0, e1)
    __shared__ float  cfs [2][16][32];       // Fs
    __shared__ float  sring[2][16][32];      // S after each step
    __shared__ float  xbuf[2][32][XPAD];     // staged x: [par][batch][16*3]

    const int tid  = threadIdx.x;
    const int lane = tid & 31;
    const int wid  = tid >> 5;               // 0 chain, 1..3 helpers
    const int b0   = blockIdx.x * 32;
    const int b    = b0 + lane;
    const float s1 = fabsf(sg1[0]);
    const float s2 = fabsf(sg2[0]);
    const float s12 = s1 + s2;

    float* __restrict__ outp = out + (size_t)b * TT;

    // copy quad table into SMEM
    for (int i = tid; i < TAB_CELLS; i += 128) tab[i] = __ldg(&g_tab4[i]);

    // helper slot assignment: w1: 0-5, w2: 6-10, w3: 11-15
    const int ns = (wid == 1) ? 6 : 5;
    const int s0 = (wid == 1) ? 0 : (wid == 2 ? 6 : 11);

    float a0 = 0.f, lvs = 0.f;

    if (wid > 0) {
        a0  = alpha[0];
        lvs = lg2f_(fabsf(vs[0]));
        const int h = tid - 32;              // 0..95
        // prologue fill: xbuf[1] <- x of iter 1 (t0 = 16), coalesced
        #pragma unroll
        for (int r = 0; r < 4; r++) {
            int idx = h + 96 * r;            // 0..383
            int bb = idx / 12, q = idx - bb * 12;
            float4 d = __ldg((const float4*)(x + ((size_t)(b0 + bb) * TT + 16) * 3 + q * 4));
            *(float4*)&xbuf[1][bb][q * 4] = d;
        }
        // records for iter 0 at pred = 0 (one-time uncoalesced loads)
        const float* __restrict__ xp = x + (size_t)b * TT * 3;
        for (int j = 0; j < ns; j++) {
            int s = s0 + j;
            sring[1][s][lane] = 0.0f;        // stale pred for n=0 build
            size_t o0 = (size_t)s * 3;
            float v0 = __ldg(xp + o0), Fc0 = __ldg(xp + o0 + 1), Fs0 = __ldg(xp + o0 + 2);
            float ca, cb, c2v;
            make_record<true>(tab, v0, Fc0, Fs0, a0, lvs, 0.0f, ca, cb, c2v);
            cab4[0][s][lane] = make_float4(ca, cb, s12 * v0, s1 * c2v * INVC);
            cfs [0][s][lane] = Fs0;
        }
    }
    __syncthreads();

    // ---------------- main loop: NIT iterations of 16 steps ----------------
    float S = 0.0f;
    float ff[4];

    for (int n = 0; n < NIT; n++) {
        if (wid == 0) {
            const int pr = n & 1;
            // rotating 4-record register window
            float4 r[4]; float fsv[4];
            #pragma unroll
            for (int j = 0; j < 4; j++) {
                r[j] = cab4[pr][j][lane];
                fsv[j] = cfs[pr][j][lane];
            }
            const int tb = n * 16;
            #pragma unroll
            for (int s = 0; s < 16; s++) {
                float4 cc = r[s & 3];
                float  Fv = fsv[s & 3];
                float szn = fmaf(cc.y, S, cc.x);
                float szc = fminf(fmaxf(szn, -Fv), Fv);
                float F   = fmaf(-cc.w, szn, cc.z) + szc;
                sring[pr][s][lane] = szc;
                S = szc;
                ff[s & 3] = F;
                if (s < 12) {                // prefetch record s+4 (>=3 steps ahead)
                    r[s & 3] = cab4[pr][s + 4][lane];
                    fsv[s & 3] = cfs[pr][s + 4][lane];
                }
                if ((s & 3) == 3)
                    *reinterpret_cast<float4*>(outp + tb + (s - 3)) =
                        make_float4(ff[0], ff[1], ff[2], ff[3]);
            }
        } else {
            const int h = tid - 32;
            // 1) coalesced fill: xbuf[n&1] <- x of iter n+2
            {
                int t0f = (n + 2) * 16; if (t0f > TT - 16) t0f = TT - 16;
                const int pf = n & 1;
                #pragma unroll
                for (int r = 0; r < 4; r++) {
                    int idx = h + 96 * r;
                    int bb = idx / 12, q = idx - bb * 12;
                    float4 d = __ldg((const float4*)(x + ((size_t)(b0 + bb) * TT + t0f) * 3 + q * 4));
                    *(float4*)&xbuf[pf][bb][q * 4] = d;
                }
            }
            // 2) build records for iter n+1 from xbuf[(n+1)&1]
            const int pw = (n + 1) & 1;
            #pragma unroll
            for (int j = 0; j < 6; j++) {
                if (j >= ns) break;
                int s = s0 + j;
                float v  = xbuf[pw][lane][s * 3];
                float Fc = xbuf[pw][lane][s * 3 + 1];
                float Fs = xbuf[pw][lane][s * 3 + 2];
                float Sp = sring[pw][s][lane];   // S_{16(n-1)+s}
                float ca, cb, c2v;
                make_record<false>(tab, v, Fc, Fs, a0, lvs, Sp, ca, cb, c2v);
                cab4[pw][s][lane] = make_float4(ca, cb, s12 * v, s1 * c2v * INVC);
                cfs [pw][s][lane] = Fs;
            }
        }
        __syncthreads();
    }
}

// ---------------- launch ----------------
extern "C" void kernel_launch(void* const* d_in, const int* in_sizes, int n_in,
                              void* d_out, int out_size) {
    const float* x     = (const float*)d_in[0];
    const float* sig1  = (const float*)d_in[1];
    const float* sig2  = (const float*)d_in[2];
    const float* alpha = (const float*)d_in[3];
    const float* vs    = (const float*)d_in[4];
    const float* W1    = (const float*)d_in[5];
    const float* b1    = (const float*)d_in[6];
    const float* W2    = (const float*)d_in[7];
    const float* b2    = (const float*)d_in[8];
    float* out = (float*)d_out;

    int ntab = (NV2 + 1) * (NS2 + 1);
    lugre_tab<<<(ntab + 255) / 256, 256>>>(W1, b1, W2, b2);
    lugre_pack<<<(TAB_CELLS + 255) / 256, 256>>>();

    cudaFuncSetAttribute(lugre_scan,
        cudaFuncAttributeMaxDynamicSharedMemorySize, TAB_BYTES);
    lugre_scan<<<128, 128, TAB_BYTES>>>(x, sig1, sig2, alpha, vs, out);
}

// round 16
// speedup vs baseline: 3.6178x; 1.1650x over previous
#include <cuda_runtime.h>
#include <cuda_bf16.h>
#include <cstdint>

// LuGreCell: B=4096, T=2048, S=1, H=64.
// K2 lugre_tab : tabulate Lg(v,sz)=softplus(MLP(v,sz))*log2e, 161x65 nodes.
// K3 lugre_pack: pack bilinear quads into float4 cells (160x64).
// K4 lugre_scan: fused warp-specialized scan, 16 steps/iteration.
//   Warp 0 = chain: rotating 4-record register window.
//   Warps 1-3 = helpers: STAGE-SPLIT record building (all loads, then all
//   gathers, then all transcendentals, then all stores) so the 5-6 records
//   per helper overlap instead of serializing their ~200-cycle chains.

#define BB 4096
#define TT 2048
#define HH 64
#define NIT (TT / 16)

// SMEM-resident table geometry
#define NV2 160
#define NS2 64
#define VMIN2   (-8.0f)
#define INV_DV2 10.0f
#define OFF_V2  80.0f
#define INV_DSZ2 12.307692307692308f   /* 64 / 5.2 */
#define OFF_S2  32.0f
#define DV2     0.1f
#define DSZ2    0.08125f
#define TAB_CELLS (NV2 * NS2)
#define TAB_BYTES (TAB_CELLS * 16)

#define XPAD 52   /* xbuf row stride in floats */

__device__ float  g_Ls[(NV2 + 1) * (NS2 + 1)];
__device__ float4 g_tab4[TAB_CELLS];

__device__ __forceinline__ float ex2f_(float x){ float y; asm("ex2.approx.f32 %0, %1;":"=f"(y):"f"(x)); return y; }
__device__ __forceinline__ float lg2f_(float x){ float y; asm("lg2.approx.f32 %0, %1;":"=f"(y):"f"(x)); return y; }
__device__ __forceinline__ float tanhf_(float x){ float y; asm("tanh.approx.f32 %0, %1;":"=f"(y):"f"(x)); return y; }

#define LOG2E 1.4426950408889634f
#define C2COEF 6.931471805599453e-4f        /* dt*ln2 */
#define INVC   1442.6950408889634f          /* 1/(dt*ln2) */

// ---------------- K2: build scalar node table ----------------
__global__ void __launch_bounds__(256) lugre_tab(
    const float* __restrict__ W1, const float* __restrict__ b1,
    const float* __restrict__ W2, const float* __restrict__ b2)
{
    int idx = blockIdx.x * blockDim.x + threadIdx.x;
    if (idx >= (NV2 + 1) * (NS2 + 1)) return;
    int iv = idx / (NS2 + 1);
    int is = idx - iv * (NS2 + 1);
    float v  = VMIN2 + (float)iv * DV2;
    float sz = -2.6f + (float)is * DSZ2;
    float y0 = 0.f, y1 = 0.f;
    #pragma unroll 8
    for (int j = 0; j < HH; j++) {
        float z = fmaf(v, __ldg(W1 + j), fmaf(sz, __ldg(W1 + HH + j), __ldg(b1 + j)));
        float h = tanhf_(z);
        if (j & 1) y1 = fmaf(h, __ldg(W2 + j), y1);
        else       y0 = fmaf(h, __ldg(W2 + j), y0);
    }
    float ys = (y0 + y1 + __ldg(b2)) * LOG2E;
    g_Ls[idx] = lg2f_(1.0f + ex2f_(ys));               // sp(y)*log2e
}

// ---------------- K3: pack quads ----------------
__global__ void __launch_bounds__(256) lugre_pack()
{
    int idx = blockIdx.x * blockDim.x + threadIdx.x;
    if (idx >= TAB_CELLS) return;
    int iv = idx / NS2;
    int is = idx - iv * NS2;
    int base = iv * (NS2 + 1) + is;
    g_tab4[idx] = make_float4(g_Ls[base], g_Ls[base + 1],
                              g_Ls[base + NS2 + 1], g_Ls[base + NS2 + 2]);
}

// ---------------- K4: fused warp-specialized scan ----------------
// prologue-only record builder (global quads)
__device__ __forceinline__ void make_record_glob(
    float v, float Fc, float Fs, float a0, float lvs, float pred,
    float& ca, float& cb, float& c2o)
{
    float av = fabsf(v);
    float pp = ex2f_(a0 * (lg2f_(av) - lvs));
    float w  = ex2f_(-LOG2E * pp);
    float g  = fmaf(Fs - Fc, w, Fc);
    float sg = (v > 0.f) ? 1.f : ((v < 0.f) ? -1.f : 0.f);
    float k  = g * sg;
    float c2 = __fdividef(av, g) * C2COEF;
    c2o = c2;
    float fv  = fmaf(v, INV_DV2, OFF_V2);
    int   iv  = (int)floorf(fv);
    iv = max(0, min(iv, NV2 - 1));
    float frv = fminf(fmaxf(fv - (float)iv, 0.f), 1.f);
    float fs  = fmaf(pred, INV_DSZ2, OFF_S2);
    int   is  = (int)floorf(fs);
    is = max(0, min(is, NS2 - 1));
    float frs = fminf(fmaxf(fs - (float)is, 0.f), 1.f);
    float4 q = __ldg(&g_tab4[iv * NS2 + is]);
    float a_  = fmaf(frv, q.z - q.x, q.x);
    float b_  = fmaf(frv, q.w - q.y, q.y);
    float Lg0 = fmaf(frs, b_ - a_, a_);
    float qs  = (b_ - a_) * INV_DSZ2;
    float u0  = c2 * Lg0;
    float m0  = u0 * fmaf(u0, fmaf(u0, 0.16666667f, -0.5f), 1.f);
    float mp  = fmaf(u0, fmaf(u0, 0.5f, -1.f), 1.f);
    float dmdS = (c2 * qs) * mp;
    float pk_ = pred - k;
    cb = fmaf(-pk_, dmdS, 1.f - m0);
    ca = fmaf(-cb, pred, fmaf(-pk_, m0, pred));
}

__global__ void __launch_bounds__(128) lugre_scan(
    const float* __restrict__ x,
    const float* __restrict__ sg1, const float* __restrict__ sg2,
    const float* __restrict__ alpha, const float* __restrict__ vs,
    float* __restrict__ out)
{
    extern __shared__ float4 tab[];          // 160KB quad table
    __shared__ float4 cab4[2][16][32];       // (ca, cb, e0, e1)
    __shared__ float  cfs [2][16][32];       // Fs
    __shared__ float  sring[2][16][32];      // S after each step
    __shared__ float  xbuf[2][32][XPAD];     // staged x

    const int tid  = threadIdx.x;
    const int lane = tid & 31;
    const int wid  = tid >> 5;               // 0 chain, 1..3 helpers
    const int b0   = blockIdx.x * 32;
    const int b    = b0 + lane;
    const float s1 = fabsf(sg1[0]);
    const float s2 = fabsf(sg2[0]);
    const float s12 = s1 + s2;

    float* __restrict__ outp = out + (size_t)b * TT;

    for (int i = tid; i < TAB_CELLS; i += 128) tab[i] = __ldg(&g_tab4[i]);

    const int ns = (wid == 1) ? 6 : 5;
    const int s0 = (wid == 1) ? 0 : (wid == 2 ? 6 : 11);

    float a0 = 0.f, lvs = 0.f;

    if (wid > 0) {
        a0  = alpha[0];
        lvs = lg2f_(fabsf(vs[0]));
        const int h = tid - 32;              // 0..95
        #pragma unroll
        for (int r = 0; r < 4; r++) {
            int idx = h + 96 * r;
            int bb = idx / 12, qd = idx - bb * 12;
            float4 d = __ldg((const float4*)(x + ((size_t)(b0 + bb) * TT + 16) * 3 + qd * 4));
            *(float4*)&xbuf[1][bb][qd * 4] = d;
        }
        const float* __restrict__ xp = x + (size_t)b * TT * 3;
        for (int j = 0; j < ns; j++) {
            int s = s0 + j;
            sring[1][s][lane] = 0.0f;
            size_t o0 = (size_t)s * 3;
            float v0 = __ldg(xp + o0), Fc0 = __ldg(xp + o0 + 1), Fs0 = __ldg(xp + o0 + 2);
            float ca, cb, c2v;
            make_record_glob(v0, Fc0, Fs0, a0, lvs, 0.0f, ca, cb, c2v);
            cab4[0][s][lane] = make_float4(ca, cb, s12 * v0, s1 * c2v * INVC);
            cfs [0][s][lane] = Fs0;
        }
    }
    __syncthreads();

    // ---------------- main loop: NIT iterations of 16 steps ----------------
    float S = 0.0f;
    float ff[4];

    for (int n = 0; n < NIT; n++) {
        if (wid == 0) {
            const int pr = n & 1;
            float4 r[4]; float fsv[4];
            #pragma unroll
            for (int j = 0; j < 4; j++) {
                r[j] = cab4[pr][j][lane];
                fsv[j] = cfs[pr][j][lane];
            }
            const int tb = n * 16;
            #pragma unroll
            for (int s = 0; s < 16; s++) {
                float4 cc = r[s & 3];
                float  Fv = fsv[s & 3];
                float szn = fmaf(cc.y, S, cc.x);
                float szc = fminf(fmaxf(szn, -Fv), Fv);
                float F   = fmaf(-cc.w, szn, cc.z) + szc;
                sring[pr][s][lane] = szc;
                S = szc;
                ff[s & 3] = F;
                if (s < 12) {
                    r[s & 3] = cab4[pr][s + 4][lane];
                    fsv[s & 3] = cfs[pr][s + 4][lane];
                }
                if ((s & 3) == 3)
                    *reinterpret_cast<float4*>(outp + tb + (s - 3)) =
                        make_float4(ff[0], ff[1], ff[2], ff[3]);
            }
        } else {
            const int h = tid - 32;
            // 1) coalesced fill: xbuf[n&1] <- x of iter n+2
            {
                int t0f = (n + 2) * 16; if (t0f > TT - 16) t0f = TT - 16;
                const int pf = n & 1;
                #pragma unroll
                for (int r = 0; r < 4; r++) {
                    int idx = h + 96 * r;
                    int bb = idx / 12, qd = idx - bb * 12;
                    float4 d = __ldg((const float4*)(x + ((size_t)(b0 + bb) * TT + t0f) * 3 + qd * 4));
                    *(float4*)&xbuf[pf][bb][qd * 4] = d;
                }
            }
            // 2) STAGE-SPLIT record building for iter n+1 (ILP across slots)
            const int pw = (n + 1) & 1;
            float v[6], Fc[6], Fv[6], Sp[6];
            // stage 1: all input loads (independent LDS)
            #pragma unroll
            for (int j = 0; j < 6; j++) {
                if (j < ns) {
                    int s = s0 + j;
                    v[j]  = xbuf[pw][lane][s * 3];
                    Fc[j] = xbuf[pw][lane][s * 3 + 1];
                    Fv[j] = xbuf[pw][lane][s * 3 + 2];
                    Sp[j] = sring[pw][s][lane];
                }
            }
            // stage 2: all table addresses + gathers
            float4 q[6]; float frv[6], frs[6];
            #pragma unroll
            for (int j = 0; j < 6; j++) {
                if (j < ns) {
                    float fv  = fmaf(v[j], INV_DV2, OFF_V2);
                    int   iv  = (int)floorf(fv);
                    iv = max(0, min(iv, NV2 - 1));
                    frv[j] = fminf(fmaxf(fv - (float)iv, 0.f), 1.f);
                    float fs  = fmaf(Sp[j], INV_DSZ2, OFF_S2);
                    int   is  = (int)floorf(fs);
                    is = max(0, min(is, NS2 - 1));
                    frs[j] = fminf(fmaxf(fs - (float)is, 0.f), 1.f);
                    q[j] = tab[iv * NS2 + is];
                }
            }
            // stage 3: all transcendental chains (MUFU interleaves across j)
            float k[6], c2[6];
            #pragma unroll
            for (int j = 0; j < 6; j++) {
                if (j < ns) {
                    float av = fabsf(v[j]);
                    float pp = ex2f_(a0 * (lg2f_(av) - lvs));
                    float w  = ex2f_(-LOG2E * pp);
                    float g  = fmaf(Fv[j] - Fc[j], w, Fc[j]);
                    float sg = (v[j] > 0.f) ? 1.f : ((v[j] < 0.f) ? -1.f : 0.f);
                    k[j]  = g * sg;
                    c2[j] = __fdividef(av, g) * C2COEF;
                }
            }
            // stage 4: final algebra + stores
            #pragma unroll
            for (int j = 0; j < 6; j++) {
                if (j < ns) {
                    int s = s0 + j;
                    float a_  = fmaf(frv[j], q[j].z - q[j].x, q[j].x);
                    float b_  = fmaf(frv[j], q[j].w - q[j].y, q[j].y);
                    float Lg0 = fmaf(frs[j], b_ - a_, a_);
                    float qs  = (b_ - a_) * INV_DSZ2;
                    float u0  = c2[j] * Lg0;
                    float m0  = u0 * fmaf(u0, fmaf(u0, 0.16666667f, -0.5f), 1.f);
                    float mp  = fmaf(u0, fmaf(u0, 0.5f, -1.f), 1.f);
                    float dmdS = (c2[j] * qs) * mp;
                    float pk_ = Sp[j] - k[j];
                    float cb = fmaf(-pk_, dmdS, 1.f - m0);
                    float ca = fmaf(-cb, Sp[j], fmaf(-pk_, m0, Sp[j]));
                    cab4[pw][s][lane] = make_float4(ca, cb, s12 * v[j], s1 * c2[j] * INVC);
                    cfs [pw][s][lane] = Fv[j];
                }
            }
        }
        __syncthreads();
    }
}

// ---------------- launch ----------------
extern "C" void kernel_launch(void* const* d_in, const int* in_sizes, int n_in,
                              void* d_out, int out_size) {
    const float* x     = (const float*)d_in[0];
    const float* sig1  = (const float*)d_in[1];
    const float* sig2  = (const float*)d_in[2];
    const float* alpha = (const float*)d_in[3];
    const float* vs    = (const float*)d_in[4];
    const float* W1    = (const float*)d_in[5];
    const float* b1    = (const float*)d_in[6];
    const float* W2    = (const float*)d_in[7];
    const float* b2    = (const float*)d_in[8];
    float* out = (float*)d_out;

    int ntab = (NV2 + 1) * (NS2 + 1);
    lugre_tab<<<(ntab + 255) / 256, 256>>>(W1, b1, W2, b2);
    lugre_pack<<<(TAB_CELLS + 255) / 256, 256>>>();

    cudaFuncSetAttribute(lugre_scan,
        cudaFuncAttributeMaxDynamicSharedMemorySize, TAB_BYTES);
    lugre_scan<<<128, 128, TAB_BYTES>>>(x, sig1, sig2, alpha, vs, out);
}

// round 17
// speedup vs baseline: 5.6377x; 1.5583x over previous
#include <cuda_runtime.h>
#include <cuda_bf16.h>
#include <cstdint>

// LuGreCell: B=4096, T=2048, S=1, H=64.
// K2 lugre_tab : tabulate Lg(v,sz)=softplus(MLP(v,sz))*log2e, 161x65 nodes.
// K3 lugre_pack: pack bilinear quads into float4 cells (160x64).
// K4 lugre_scan: fused warp-specialized scan, 16 steps/iteration.
//   Warp 0 = chain: rotating 4-record register window.
//   Warps 1-3 = helpers: stage-split record building + REGISTER-STAGED
//   double-distance x prefetch: LDG (iter n, x of iter n+3) -> regs ->
//   STS (iter n+1) -> consumed (iter n+2). DRAM latency fully in flight.

#define BB 4096
#define TT 2048
#define HH 64
#define NIT (TT / 16)

// SMEM-resident table geometry
#define NV2 160
#define NS2 64
#define VMIN2   (-8.0f)
#define INV_DV2 10.0f
#define OFF_V2  80.0f
#define INV_DSZ2 12.307692307692308f   /* 64 / 5.2 */
#define OFF_S2  32.0f
#define DV2     0.1f
#define DSZ2    0.08125f
#define TAB_CELLS (NV2 * NS2)
#define TAB_BYTES (TAB_CELLS * 16)

#define XPAD 52   /* xbuf row stride in floats */

__device__ float  g_Ls[(NV2 + 1) * (NS2 + 1)];
__device__ float4 g_tab4[TAB_CELLS];

__device__ __forceinline__ float ex2f_(float x){ float y; asm("ex2.approx.f32 %0, %1;":"=f"(y):"f"(x)); return y; }
__device__ __forceinline__ float lg2f_(float x){ float y; asm("lg2.approx.f32 %0, %1;":"=f"(y):"f"(x)); return y; }
__device__ __forceinline__ float tanhf_(float x){ float y; asm("tanh.approx.f32 %0, %1;":"=f"(y):"f"(x)); return y; }

#define LOG2E 1.4426950408889634f
#define C2COEF 6.931471805599453e-4f        /* dt*ln2 */
#define INVC   1442.6950408889634f          /* 1/(dt*ln2) */

// ---------------- K2: build scalar node table ----------------
__global__ void __launch_bounds__(256) lugre_tab(
    const float* __restrict__ W1, const float* __restrict__ b1,
    const float* __restrict__ W2, const float* __restrict__ b2)
{
    int idx = blockIdx.x * blockDim.x + threadIdx.x;
    if (idx >= (NV2 + 1) * (NS2 + 1)) return;
    int iv = idx / (NS2 + 1);
    int is = idx - iv * (NS2 + 1);
    float v  = VMIN2 + (float)iv * DV2;
    float sz = -2.6f + (float)is * DSZ2;
    float y0 = 0.f, y1 = 0.f;
    #pragma unroll 8
    for (int j = 0; j < HH; j++) {
        float z = fmaf(v, __ldg(W1 + j), fmaf(sz, __ldg(W1 + HH + j), __ldg(b1 + j)));
        float h = tanhf_(z);
        if (j & 1) y1 = fmaf(h, __ldg(W2 + j), y1);
        else       y0 = fmaf(h, __ldg(W2 + j), y0);
    }
    float ys = (y0 + y1 + __ldg(b2)) * LOG2E;
    g_Ls[idx] = lg2f_(1.0f + ex2f_(ys));               // sp(y)*log2e
}

// ---------------- K3: pack quads ----------------
__global__ void __launch_bounds__(256) lugre_pack()
{
    int idx = blockIdx.x * blockDim.x + threadIdx.x;
    if (idx >= TAB_CELLS) return;
    int iv = idx / NS2;
    int is = idx - iv * NS2;
    int base = iv * (NS2 + 1) + is;
    g_tab4[idx] = make_float4(g_Ls[base], g_Ls[base + 1],
                              g_Ls[base + NS2 + 1], g_Ls[base + NS2 + 2]);
}

// ---------------- K4: fused warp-specialized scan ----------------
__device__ __forceinline__ void make_record_glob(
    float v, float Fc, float Fs, float a0, float lvs, float pred,
    float& ca, float& cb, float& c2o)
{
    float av = fabsf(v);
    float pp = ex2f_(a0 * (lg2f_(av) - lvs));
    float w  = ex2f_(-LOG2E * pp);
    float g  = fmaf(Fs - Fc, w, Fc);
    float sg = (v > 0.f) ? 1.f : ((v < 0.f) ? -1.f : 0.f);
    float k  = g * sg;
    float c2 = __fdividef(av, g) * C2COEF;
    c2o = c2;
    float fv  = fmaf(v, INV_DV2, OFF_V2);
    int   iv  = (int)floorf(fv);
    iv = max(0, min(iv, NV2 - 1));
    float frv = fminf(fmaxf(fv - (float)iv, 0.f), 1.f);
    float fs  = fmaf(pred, INV_DSZ2, OFF_S2);
    int   is  = (int)floorf(fs);
    is = max(0, min(is, NS2 - 1));
    float frs = fminf(fmaxf(fs - (float)is, 0.f), 1.f);
    float4 q = __ldg(&g_tab4[iv * NS2 + is]);
    float a_  = fmaf(frv, q.z - q.x, q.x);
    float b_  = fmaf(frv, q.w - q.y, q.y);
    float Lg0 = fmaf(frs, b_ - a_, a_);
    float qs  = (b_ - a_) * INV_DSZ2;
    float u0  = c2 * Lg0;
    float m0  = u0 * fmaf(u0, fmaf(u0, 0.16666667f, -0.5f), 1.f);
    float mp  = fmaf(u0, fmaf(u0, 0.5f, -1.f), 1.f);
    float dmdS = (c2 * qs) * mp;
    float pk_ = pred - k;
    cb = fmaf(-pk_, dmdS, 1.f - m0);
    ca = fmaf(-cb, pred, fmaf(-pk_, m0, pred));
}

__global__ void __launch_bounds__(128) lugre_scan(
    const float* __restrict__ x,
    const float* __restrict__ sg1, const float* __restrict__ sg2,
    const float* __restrict__ alpha, const float* __restrict__ vs,
    float* __restrict__ out)
{
    extern __shared__ float4 tab[];          // 160KB quad table
    __shared__ float4 cab4[2][16][32];       // (ca, cb, e0, e1)
    __shared__ float  cfs [2][16][32];       // Fs
    __shared__ float  sring[2][16][32];      // S after each step
    __shared__ float  xbuf[2][32][XPAD];     // staged x

    const int tid  = threadIdx.x;
    const int lane = tid & 31;
    const int wid  = tid >> 5;               // 0 chain, 1..3 helpers
    const int b0   = blockIdx.x * 32;
    const int b    = b0 + lane;
    const float s1 = fabsf(sg1[0]);
    const float s2 = fabsf(sg2[0]);
    const float s12 = s1 + s2;

    float* __restrict__ outp = out + (size_t)b * TT;

    for (int i = tid; i < TAB_CELLS; i += 128) tab[i] = __ldg(&g_tab4[i]);

    const int ns = (wid == 1) ? 6 : 5;
    const int s0 = (wid == 1) ? 0 : (wid == 2 ? 6 : 11);

    float a0 = 0.f, lvs = 0.f;
    float4 dreg[4];                           // register-staged x block
    int hb[4], hq[4];                         // per-thread fill coords

    if (wid > 0) {
        a0  = alpha[0];
        lvs = lg2f_(fabsf(vs[0]));
        const int h = tid - 32;              // 0..95
        #pragma unroll
        for (int r = 0; r < 4; r++) {
            int idx = h + 96 * r;            // 0..383
            hb[r] = idx / 12;
            hq[r] = idx - hb[r] * 12;
        }
        // direct fill: xbuf[1] <- x of iter 1 (t0 = 16)
        #pragma unroll
        for (int r = 0; r < 4; r++) {
            float4 d = __ldg((const float4*)(x + ((size_t)(b0 + hb[r]) * TT + 16) * 3 + hq[r] * 4));
            *(float4*)&xbuf[1][hb[r]][hq[r] * 4] = d;
        }
        // register preload: dreg <- x of iter 2 (t0 = 32)
        #pragma unroll
        for (int r = 0; r < 4; r++)
            dreg[r] = __ldg((const float4*)(x + ((size_t)(b0 + hb[r]) * TT + 32) * 3 + hq[r] * 4));
        // records for iter 0 at pred = 0
        const float* __restrict__ xp = x + (size_t)b * TT * 3;
        for (int j = 0; j < ns; j++) {
            int s = s0 + j;
            sring[1][s][lane] = 0.0f;
            size_t o0 = (size_t)s * 3;
            float v0 = __ldg(xp + o0), Fc0 = __ldg(xp + o0 + 1), Fs0 = __ldg(xp + o0 + 2);
            float ca, cb, c2v;
            make_record_glob(v0, Fc0, Fs0, a0, lvs, 0.0f, ca, cb, c2v);
            cab4[0][s][lane] = make_float4(ca, cb, s12 * v0, s1 * c2v * INVC);
            cfs [0][s][lane] = Fs0;
        }
    }
    __syncthreads();

    // ---------------- main loop: NIT iterations of 16 steps ----------------
    float S = 0.0f;
    float ff[4];

    for (int n = 0; n < NIT; n++) {
        if (wid == 0) {
            const int pr = n & 1;
            float4 r[4]; float fsv[4];
            #pragma unroll
            for (int j = 0; j < 4; j++) {
                r[j] = cab4[pr][j][lane];
                fsv[j] = cfs[pr][j][lane];
            }
            const int tb = n * 16;
            #pragma unroll
            for (int s = 0; s < 16; s++) {
                float4 cc = r[s & 3];
                float  Fv = fsv[s & 3];
                float szn = fmaf(cc.y, S, cc.x);
                float szc = fminf(fmaxf(szn, -Fv), Fv);
                float F   = fmaf(-cc.w, szn, cc.z) + szc;
                sring[pr][s][lane] = szc;
                S = szc;
                ff[s & 3] = F;
                if (s < 12) {
                    r[s & 3] = cab4[pr][s + 4][lane];
                    fsv[s & 3] = cfs[pr][s + 4][lane];
                }
                if ((s & 3) == 3)
                    *reinterpret_cast<float4*>(outp + tb + (s - 3)) =
                        make_float4(ff[0], ff[1], ff[2], ff[3]);
            }
        } else {
            // 1) STS: xbuf[n&1] <- dreg (x of iter n+2, loaded at iter n-1)
            const int pf = n & 1;
            #pragma unroll
            for (int r = 0; r < 4; r++)
                *(float4*)&xbuf[pf][hb[r]][hq[r] * 4] = dreg[r];
            // 2) LDG: dreg <- x of iter n+3 (a full iteration in flight)
            {
                int t0f = (n + 3) * 16; if (t0f > TT - 16) t0f = TT - 16;
                #pragma unroll
                for (int r = 0; r < 4; r++)
                    dreg[r] = __ldg((const float4*)(x + ((size_t)(b0 + hb[r]) * TT + t0f) * 3 + hq[r] * 4));
            }
            // 3) stage-split record building for iter n+1
            const int pw = (n + 1) & 1;
            float v[6], Fc[6], Fv[6], Sp[6];
            #pragma unroll
            for (int j = 0; j < 6; j++) {
                if (j < ns) {
                    int s = s0 + j;
                    v[j]  = xbuf[pw][lane][s * 3];
                    Fc[j] = xbuf[pw][lane][s * 3 + 1];
                    Fv[j] = xbuf[pw][lane][s * 3 + 2];
                    Sp[j] = sring[pw][s][lane];
                }
            }
            float4 q[6]; float frv[6], frs[6];
            #pragma unroll
            for (int j = 0; j < 6; j++) {
                if (j < ns) {
                    float fv  = fmaf(v[j], INV_DV2, OFF_V2);
                    int   iv  = (int)floorf(fv);
                    iv = max(0, min(iv, NV2 - 1));
                    frv[j] = fminf(fmaxf(fv - (float)iv, 0.f), 1.f);
                    float fs  = fmaf(Sp[j], INV_DSZ2, OFF_S2);
                    int   is  = (int)floorf(fs);
                    is = max(0, min(is, NS2 - 1));
                    frs[j] = fminf(fmaxf(fs - (float)is, 0.f), 1.f);
                    q[j] = tab[iv * NS2 + is];
                }
            }
            float k[6], c2[6];
            #pragma unroll
            for (int j = 0; j < 6; j++) {
                if (j < ns) {
                    float av = fabsf(v[j]);
                    float pp = ex2f_(a0 * (lg2f_(av) - lvs));
                    float w  = ex2f_(-LOG2E * pp);
                    float g  = fmaf(Fv[j] - Fc[j], w, Fc[j]);
                    float sg = (v[j] > 0.f) ? 1.f : ((v[j] < 0.f) ? -1.f : 0.f);
                    k[j]  = g * sg;
                    c2[j] = __fdividef(av, g) * C2COEF;
                }
            }
            #pragma unroll
            for (int j = 0; j < 6; j++) {
                if (j < ns) {
                    int s = s0 + j;
                    float a_  = fmaf(frv[j], q[j].z - q[j].x, q[j].x);
                    float b_  = fmaf(frv[j], q[j].w - q[j].y, q[j].y);
                    float Lg0 = fmaf(frs[j], b_ - a_, a_);
                    float qs  = (b_ - a_) * INV_DSZ2;
                    float u0  = c2[j] * Lg0;
                    float m0  = u0 * fmaf(u0, fmaf(u0, 0.16666667f, -0.5f), 1.f);
                    float mp  = fmaf(u0, fmaf(u0, 0.5f, -1.f), 1.f);
                    float dmdS = (c2[j] * qs) * mp;
                    float pk_ = Sp[j] - k[j];
                    float cb = fmaf(-pk_, dmdS, 1.f - m0);
                    float ca = fmaf(-cb, Sp[j], fmaf(-pk_, m0, Sp[j]));
                    cab4[pw][s][lane] = make_float4(ca, cb, s12 * v[j], s1 * c2[j] * INVC);
                    cfs [pw][s][lane] = Fv[j];
                }
            }
        }
        __syncthreads();
    }
}

// ---------------- launch ----------------
extern "C" void kernel_launch(void* const* d_in, const int* in_sizes, int n_in,
                              void* d_out, int out_size) {
    const float* x     = (const float*)d_in[0];
    const float* sig1  = (const float*)d_in[1];
    const float* sig2  = (const float*)d_in[2];
    const float* alpha = (const float*)d_in[3];
    const float* vs    = (const float*)d_in[4];
    const float* W1    = (const float*)d_in[5];
    const float* b1    = (const float*)d_in[6];
    const float* W2    = (const float*)d_in[7];
    const float* b2    = (const float*)d_in[8];
    float* out = (float*)d_out;

    int ntab = (NV2 + 1) * (NS2 + 1);
    lugre_tab<<<(ntab + 255) / 256, 256>>>(W1, b1, W2, b2);
    lugre_pack<<<(TAB_CELLS + 255) / 256, 256>>>();

    cudaFuncSetAttribute(lugre_scan,
        cudaFuncAttributeMaxDynamicSharedMemorySize, TAB_BYTES);
    lugre_scan<<<128, 128, TAB_BYTES>>>(x, sig1, sig2, alpha, vs, out);
}